// round 1
// baseline (speedup 1.0000x reference)
#include <cuda_runtime.h>
#include <math.h>

#define B_  2
#define S_  2048
#define D_  1024
#define H_  16
#define DK_ 64
#define BS_ (B_*S_)   // 4096

// ---------------- scratch (static device allocations are allowed) ----------
__device__ float g_Qh[B_*H_*S_*DK_];   // [B,H,S,DK]
__device__ float g_Kh[B_*H_*S_*DK_];
__device__ float g_Vh[B_*H_*S_*DK_];
__device__ float g_ctx[BS_*D_];        // concat [B,S,D]
__device__ float g_x[BS_*D_];          // pre-LN (out + residual)

// ===========================================================================
// Projection GEMM: C = X @ W^T + bias, scattered to head layout [B,H,S,DK]
// X: [BS, D] row-major, W: [D, D] row-major (W[n][k]).
// 128x128 block, 8x8 per thread, BK=16.
// ===========================================================================
__global__ __launch_bounds__(256) void proj_kernel(const float* __restrict__ X,
                                                   const float* __restrict__ W,
                                                   const float* __restrict__ bias,
                                                   int which)
{
    __shared__ float As[16][132];
    __shared__ float Bs[16][132];
    float* outp = (which == 0) ? g_Qh : (which == 1) ? g_Kh : g_Vh;

    const int bm = blockIdx.y * 128;
    const int bn = blockIdx.x * 128;
    const int t  = threadIdx.x;
    const int ty = t >> 4;        // 0..15
    const int tx = t & 15;        // 0..15

    float acc[8][8];
#pragma unroll
    for (int i = 0; i < 8; i++)
#pragma unroll
        for (int j = 0; j < 8; j++) acc[i][j] = 0.f;

    for (int k0 = 0; k0 < D_; k0 += 16) {
#pragma unroll
        for (int i = 0; i < 2; i++) {
            int l4  = t + 256 * i;          // 0..511
            int row = l4 >> 2;              // 0..127
            int kg  = (l4 & 3) << 2;        // 0,4,8,12
            float4 xa = *(const float4*)(X + (size_t)(bm + row) * D_ + k0 + kg);
            As[kg + 0][row] = xa.x; As[kg + 1][row] = xa.y;
            As[kg + 2][row] = xa.z; As[kg + 3][row] = xa.w;
            float4 wa = *(const float4*)(W + (size_t)(bn + row) * D_ + k0 + kg);
            Bs[kg + 0][row] = wa.x; Bs[kg + 1][row] = wa.y;
            Bs[kg + 2][row] = wa.z; Bs[kg + 3][row] = wa.w;
        }
        __syncthreads();
#pragma unroll
        for (int kk = 0; kk < 16; kk++) {
            float a[8], b[8];
#pragma unroll
            for (int i = 0; i < 8; i++) a[i] = As[kk][ty * 8 + i];
#pragma unroll
            for (int j = 0; j < 8; j++) b[j] = Bs[kk][tx * 8 + j];
#pragma unroll
            for (int i = 0; i < 8; i++)
#pragma unroll
                for (int j = 0; j < 8; j++) acc[i][j] = fmaf(a[i], b[j], acc[i][j]);
        }
        __syncthreads();
    }

    // epilogue: scatter to [B,H,S,DK]
#pragma unroll
    for (int i = 0; i < 8; i++) {
        int m    = bm + ty * 8 + i;
        int bidx = m >> 11;        // /S_
        int s    = m & (S_ - 1);
#pragma unroll
        for (int j = 0; j < 8; j++) {
            int n  = bn + tx * 8 + j;
            int h  = n >> 6;       // /DK_
            int dk = n & (DK_ - 1);
            outp[(((size_t)(bidx * H_ + h)) * S_ + s) * DK_ + dk] = acc[i][j] + bias[n];
        }
    }
}

// ===========================================================================
// Output projection: x = g_ctx @ Wo^T + bo + residual -> g_x  [BS, D]
// ===========================================================================
__global__ __launch_bounds__(256) void outproj_kernel(const float* __restrict__ W,
                                                      const float* __restrict__ bias,
                                                      const float* __restrict__ res)
{
    __shared__ float As[16][132];
    __shared__ float Bs[16][132];

    const int bm = blockIdx.y * 128;
    const int bn = blockIdx.x * 128;
    const int t  = threadIdx.x;
    const int ty = t >> 4;
    const int tx = t & 15;

    float acc[8][8];
#pragma unroll
    for (int i = 0; i < 8; i++)
#pragma unroll
        for (int j = 0; j < 8; j++) acc[i][j] = 0.f;

    for (int k0 = 0; k0 < D_; k0 += 16) {
#pragma unroll
        for (int i = 0; i < 2; i++) {
            int l4  = t + 256 * i;
            int row = l4 >> 2;
            int kg  = (l4 & 3) << 2;
            float4 xa = *(const float4*)(g_ctx + (size_t)(bm + row) * D_ + k0 + kg);
            As[kg + 0][row] = xa.x; As[kg + 1][row] = xa.y;
            As[kg + 2][row] = xa.z; As[kg + 3][row] = xa.w;
            float4 wa = *(const float4*)(W + (size_t)(bn + row) * D_ + k0 + kg);
            Bs[kg + 0][row] = wa.x; Bs[kg + 1][row] = wa.y;
            Bs[kg + 2][row] = wa.z; Bs[kg + 3][row] = wa.w;
        }
        __syncthreads();
#pragma unroll
        for (int kk = 0; kk < 16; kk++) {
            float a[8], b[8];
#pragma unroll
            for (int i = 0; i < 8; i++) a[i] = As[kk][ty * 8 + i];
#pragma unroll
            for (int j = 0; j < 8; j++) b[j] = Bs[kk][tx * 8 + j];
#pragma unroll
            for (int i = 0; i < 8; i++)
#pragma unroll
                for (int j = 0; j < 8; j++) acc[i][j] = fmaf(a[i], b[j], acc[i][j]);
        }
        __syncthreads();
    }

#pragma unroll
    for (int i = 0; i < 8; i++) {
        int m = bm + ty * 8 + i;
#pragma unroll
        for (int j = 0; j < 8; j++) {
            int n = bn + tx * 8 + j;
            g_x[(size_t)m * D_ + n] = acc[i][j] + bias[n] + res[(size_t)m * D_ + n];
        }
    }
}

// ===========================================================================
// Flash attention: per (q-tile 64, h, b). K/V tiles of 64, online softmax.
// 256 threads, 4x4 micro-tile. Writes ctx in concat layout [B,S,D].
// ===========================================================================
__global__ __launch_bounds__(256) void flash_kernel(const int* __restrict__ mask)
{
    extern __shared__ float sm[];
    float* Qs = sm;                 // 64 x 65
    float* Ks = sm + 64 * 65;
    float* Vs = sm + 2 * 64 * 65;
    float* Ps = sm + 3 * 64 * 65;

    const int b  = blockIdx.z;
    const int h  = blockIdx.y;
    const int q0 = blockIdx.x * 64;
    const int t  = threadIdx.x;
    const int rg = t >> 4;          // 0..15  (4 rows each)
    const int cg = t & 15;          // 0..15  (4 cols each)

    const float* Qg = g_Qh + ((size_t)(b * H_ + h)) * S_ * DK_;
    const float* Kg = g_Kh + ((size_t)(b * H_ + h)) * S_ * DK_;
    const float* Vg = g_Vh + ((size_t)(b * H_ + h)) * S_ * DK_;

    // load Q tile once
#pragma unroll
    for (int i = 0; i < 4; i++) {
        int l4  = t + 256 * i;      // 0..1023
        int row = l4 >> 4;          // 0..63
        int dg  = (l4 & 15) << 2;   // 0..60
        float4 qa = *(const float4*)(Qg + (size_t)(q0 + row) * DK_ + dg);
        Qs[row * 65 + dg + 0] = qa.x; Qs[row * 65 + dg + 1] = qa.y;
        Qs[row * 65 + dg + 2] = qa.z; Qs[row * 65 + dg + 3] = qa.w;
    }

    float m_i[4], l_i[4], acc[4][4];
#pragma unroll
    for (int i = 0; i < 4; i++) {
        m_i[i] = -1e30f; l_i[i] = 0.f;
#pragma unroll
        for (int j = 0; j < 4; j++) acc[i][j] = 0.f;
    }

    for (int k0 = 0; k0 < S_; k0 += 64) {
#pragma unroll
        for (int i = 0; i < 4; i++) {
            int l4  = t + 256 * i;
            int row = l4 >> 4;
            int dg  = (l4 & 15) << 2;
            float4 ka = *(const float4*)(Kg + (size_t)(k0 + row) * DK_ + dg);
            Ks[row * 65 + dg + 0] = ka.x; Ks[row * 65 + dg + 1] = ka.y;
            Ks[row * 65 + dg + 2] = ka.z; Ks[row * 65 + dg + 3] = ka.w;
            float4 va = *(const float4*)(Vg + (size_t)(k0 + row) * DK_ + dg);
            Vs[row * 65 + dg + 0] = va.x; Vs[row * 65 + dg + 1] = va.y;
            Vs[row * 65 + dg + 2] = va.z; Vs[row * 65 + dg + 3] = va.w;
        }
        __syncthreads();

        // scores: S = Q @ K^T  (4x4 per thread)
        float s[4][4];
#pragma unroll
        for (int i = 0; i < 4; i++)
#pragma unroll
            for (int j = 0; j < 4; j++) s[i][j] = 0.f;

#pragma unroll 4
        for (int d = 0; d < 64; d++) {
            float a0 = Qs[(rg * 4 + 0) * 65 + d];
            float a1 = Qs[(rg * 4 + 1) * 65 + d];
            float a2 = Qs[(rg * 4 + 2) * 65 + d];
            float a3 = Qs[(rg * 4 + 3) * 65 + d];
            float b0 = Ks[(cg * 4 + 0) * 65 + d];
            float b1 = Ks[(cg * 4 + 1) * 65 + d];
            float b2 = Ks[(cg * 4 + 2) * 65 + d];
            float b3 = Ks[(cg * 4 + 3) * 65 + d];
            s[0][0] = fmaf(a0, b0, s[0][0]); s[0][1] = fmaf(a0, b1, s[0][1]);
            s[0][2] = fmaf(a0, b2, s[0][2]); s[0][3] = fmaf(a0, b3, s[0][3]);
            s[1][0] = fmaf(a1, b0, s[1][0]); s[1][1] = fmaf(a1, b1, s[1][1]);
            s[1][2] = fmaf(a1, b2, s[1][2]); s[1][3] = fmaf(a1, b3, s[1][3]);
            s[2][0] = fmaf(a2, b0, s[2][0]); s[2][1] = fmaf(a2, b1, s[2][1]);
            s[2][2] = fmaf(a2, b2, s[2][2]); s[2][3] = fmaf(a2, b3, s[2][3]);
            s[3][0] = fmaf(a3, b0, s[3][0]); s[3][1] = fmaf(a3, b1, s[3][1]);
            s[3][2] = fmaf(a3, b2, s[3][2]); s[3][3] = fmaf(a3, b3, s[3][3]);
        }

        // scale + mask
        const float scale = 0.125f;   // 1/sqrt(64)
#pragma unroll
        for (int i = 0; i < 4; i++) {
            const int* mrow = mask + ((size_t)b * S_ + (q0 + rg * 4 + i)) * S_ + k0;
#pragma unroll
            for (int j = 0; j < 4; j++) {
                float val = s[i][j] * scale;
                s[i][j] = (mrow[cg * 4 + j] == 0) ? -1e9f : val;
            }
        }

        // online softmax (row stats shared by 16 lanes via shfl within 16-group)
#pragma unroll
        for (int i = 0; i < 4; i++) {
            float mx = fmaxf(fmaxf(s[i][0], s[i][1]), fmaxf(s[i][2], s[i][3]));
#pragma unroll
            for (int off = 8; off >= 1; off >>= 1)
                mx = fmaxf(mx, __shfl_xor_sync(0xffffffffu, mx, off));
            float mnew = fmaxf(m_i[i], mx);
            float p0 = __expf(s[i][0] - mnew);
            float p1 = __expf(s[i][1] - mnew);
            float p2 = __expf(s[i][2] - mnew);
            float p3 = __expf(s[i][3] - mnew);
            float rs = p0 + p1 + p2 + p3;
#pragma unroll
            for (int off = 8; off >= 1; off >>= 1)
                rs += __shfl_xor_sync(0xffffffffu, rs, off);
            float f = __expf(m_i[i] - mnew);
            l_i[i] = l_i[i] * f + rs;
            m_i[i] = mnew;
            acc[i][0] *= f; acc[i][1] *= f; acc[i][2] *= f; acc[i][3] *= f;
            float* prow = Ps + (rg * 4 + i) * 65 + cg * 4;
            prow[0] = p0; prow[1] = p1; prow[2] = p2; prow[3] = p3;
        }
        __syncthreads();

        // acc += P @ V   (thread owns same 4 rows, dk cols cg*4..+3)
#pragma unroll 4
        for (int c = 0; c < 64; c++) {
            float p0 = Ps[(rg * 4 + 0) * 65 + c];
            float p1 = Ps[(rg * 4 + 1) * 65 + c];
            float p2 = Ps[(rg * 4 + 2) * 65 + c];
            float p3 = Ps[(rg * 4 + 3) * 65 + c];
            float v0 = Vs[c * 65 + cg * 4 + 0];
            float v1 = Vs[c * 65 + cg * 4 + 1];
            float v2 = Vs[c * 65 + cg * 4 + 2];
            float v3 = Vs[c * 65 + cg * 4 + 3];
            acc[0][0] = fmaf(p0, v0, acc[0][0]); acc[0][1] = fmaf(p0, v1, acc[0][1]);
            acc[0][2] = fmaf(p0, v2, acc[0][2]); acc[0][3] = fmaf(p0, v3, acc[0][3]);
            acc[1][0] = fmaf(p1, v0, acc[1][0]); acc[1][1] = fmaf(p1, v1, acc[1][1]);
            acc[1][2] = fmaf(p1, v2, acc[1][2]); acc[1][3] = fmaf(p1, v3, acc[1][3]);
            acc[2][0] = fmaf(p2, v0, acc[2][0]); acc[2][1] = fmaf(p2, v1, acc[2][1]);
            acc[2][2] = fmaf(p2, v2, acc[2][2]); acc[2][3] = fmaf(p2, v3, acc[2][3]);
            acc[3][0] = fmaf(p3, v0, acc[3][0]); acc[3][1] = fmaf(p3, v1, acc[3][1]);
            acc[3][2] = fmaf(p3, v2, acc[3][2]); acc[3][3] = fmaf(p3, v3, acc[3][3]);
        }
        __syncthreads();
    }

    // write ctx in concat layout [B,S,D]
#pragma unroll
    for (int i = 0; i < 4; i++) {
        float inv = 1.0f / l_i[i];
        int row = q0 + rg * 4 + i;
        float* orow = g_ctx + ((size_t)b * S_ + row) * D_ + h * DK_ + cg * 4;
        orow[0] = acc[i][0] * inv; orow[1] = acc[i][1] * inv;
        orow[2] = acc[i][2] * inv; orow[3] = acc[i][3] * inv;
    }
}

// ===========================================================================
// LayerNorm over D=1024 per row: out = (x - mu)/sqrt(var+eps)*gamma + beta
// ===========================================================================
__global__ __launch_bounds__(256) void ln_kernel(const float* __restrict__ gamma,
                                                 const float* __restrict__ beta,
                                                 float* __restrict__ out)
{
    const int row = blockIdx.x;
    const int t   = threadIdx.x;
    const float* x = g_x + (size_t)row * D_;

    float4 v = *(const float4*)(x + t * 4);
    float s  = v.x + v.y + v.z + v.w;
    float ss = v.x * v.x + v.y * v.y + v.z * v.z + v.w * v.w;
#pragma unroll
    for (int off = 16; off >= 1; off >>= 1) {
        s  += __shfl_xor_sync(0xffffffffu, s,  off);
        ss += __shfl_xor_sync(0xffffffffu, ss, off);
    }
    __shared__ float red[8][2];
    int w = t >> 5, ln = t & 31;
    if (ln == 0) { red[w][0] = s; red[w][1] = ss; }
    __syncthreads();
    s = 0.f; ss = 0.f;
#pragma unroll
    for (int i = 0; i < 8; i++) { s += red[i][0]; ss += red[i][1]; }

    float mean = s * (1.0f / D_);
    float var  = ss * (1.0f / D_) - mean * mean;
    float rstd = rsqrtf(var + 1e-5f);

    float4 g  = *(const float4*)(gamma + t * 4);
    float4 be = *(const float4*)(beta + t * 4);
    float4 o;
    o.x = (v.x - mean) * rstd * g.x + be.x;
    o.y = (v.y - mean) * rstd * g.y + be.y;
    o.z = (v.z - mean) * rstd * g.z + be.z;
    o.w = (v.w - mean) * rstd * g.w + be.w;
    *(float4*)(out + (size_t)row * D_ + t * 4) = o;
}

// ===========================================================================
extern "C" void kernel_launch(void* const* d_in, const int* in_sizes, int n_in,
                              void* d_out, int out_size)
{
    const float* q     = (const float*)d_in[0];
    const float* k     = (const float*)d_in[1];
    const float* v     = (const float*)d_in[2];
    const int*   mask  = (const int*)  d_in[3];
    const float* Wq    = (const float*)d_in[4];
    const float* bq    = (const float*)d_in[5];
    const float* Wk    = (const float*)d_in[6];
    const float* bk    = (const float*)d_in[7];
    const float* Wv    = (const float*)d_in[8];
    const float* bv    = (const float*)d_in[9];
    const float* Wo    = (const float*)d_in[10];
    const float* bo    = (const float*)d_in[11];
    const float* gamma = (const float*)d_in[12];
    const float* beta  = (const float*)d_in[13];
    float* out = (float*)d_out;

    dim3 gGemm(D_ / 128, BS_ / 128);       // (8, 32)
    proj_kernel<<<gGemm, 256>>>(q, Wq, bq, 0);
    proj_kernel<<<gGemm, 256>>>(k, Wk, bk, 1);
    proj_kernel<<<gGemm, 256>>>(v, Wv, bv, 2);

    int smem = 4 * 64 * 65 * sizeof(float);  // 66560
    cudaFuncSetAttribute(flash_kernel, cudaFuncAttributeMaxDynamicSharedMemorySize, smem);
    dim3 gFlash(S_ / 64, H_, B_);            // (32, 16, 2)
    flash_kernel<<<gFlash, 256, smem>>>(mask);

    outproj_kernel<<<gGemm, 256>>>(Wo, bo, q);

    ln_kernel<<<BS_, 256>>>(gamma, beta, out);
}

// round 9
// speedup vs baseline: 1.1238x; 1.1238x over previous
#include <cuda_runtime.h>
#include <cuda_bf16.h>
#include <mma.h>
#include <math.h>

using namespace nvcuda;

#define B_  2
#define S_  2048
#define D_  1024
#define H_  16
#define DK_ 64
#define BS_ (B_*S_)   // 4096

// ---------------- scratch ----------------
__device__ float g_Qh[B_*H_*S_*DK_];   // [B,H,S,DK]
__device__ float g_Kh[B_*H_*S_*DK_];
__device__ float g_Vh[B_*H_*S_*DK_];
__device__ float g_ctx[BS_*D_];        // concat [B,S,D]
__device__ float g_x[BS_*D_];          // pre-LN (out + residual)

typedef __nv_bfloat16 bf16;

__device__ __forceinline__ void split2(float x, bf16& hi, bf16& lo) {
    hi = __float2bfloat16(x);
    lo = __float2bfloat16(x - __bfloat162float(hi));
}

typedef wmma::fragment<wmma::matrix_a, 16, 16, 16, bf16, wmma::row_major> FragA;
typedef wmma::fragment<wmma::matrix_b, 16, 16, 16, bf16, wmma::col_major> FragBc;
typedef wmma::fragment<wmma::matrix_b, 16, 16, 16, bf16, wmma::row_major> FragBr;
typedef wmma::fragment<wmma::accumulator, 16, 16, 16, float> FragC;

// ===========================================================================
// bf16-split GEMM: C = X @ W^T (+bias [+res]); BM=128, BN=64, BK=32.
// 8 warps 4(m) x 2(n); warp tile 32x32 = 4 named acc fragments.
// mode 0: scatter to head layout [B,H,S,DK]  (X = host-provided input)
// mode 1: g_x = C + bias + res               (X := g_ctx, resolved DEVICE-side)
// ===========================================================================
#define GKS 32   // bf16 tile k-stride (elems)
#define CST 72   // fp32 C stride

__global__ void gemm_tc(const float* __restrict__ Xin,
                        const float* __restrict__ W,
                        const float* __restrict__ bias,
                        const float* __restrict__ res,
                        int mode, int which)
{
    __shared__ __align__(32) char gsm[128 * CST * 4];   // 36864 B
    bf16* Ah = (bf16*)gsm;                    // [128][GKS]
    bf16* Al = Ah + 128 * GKS;
    bf16* Bh = Al + 128 * GKS;                // [64][GKS]
    bf16* Bl = Bh + 64 * GKS;
    float* Cs = (float*)gsm;                  // epilogue reuse [128][CST]

    // device-side symbol resolution (NEVER pass __device__ symbols from host)
    const float* X = (mode == 1) ? (const float*)g_ctx : Xin;
    float* outp = (which == 0) ? g_Qh : (which == 1) ? g_Kh : g_Vh;

    const int bm = blockIdx.y * 128;
    const int bn = blockIdx.x * 64;
    const int t  = threadIdx.x;
    const int w  = t >> 5;
    const int wm = (w & 3) * 32;
    const int wn = (w >> 2) * 32;

    FragC acc00, acc01, acc10, acc11;
    wmma::fill_fragment(acc00, 0.f);
    wmma::fill_fragment(acc01, 0.f);
    wmma::fill_fragment(acc10, 0.f);
    wmma::fill_fragment(acc11, 0.f);

    for (int k0 = 0; k0 < D_; k0 += 32) {
        // A tile 128x32: 1024 float4 -> 4/thread
#pragma unroll
        for (int i = 0; i < 4; i++) {
            int idx = t + 256 * i;
            int row = idx >> 3;
            int kg  = (idx & 7) << 2;
            float4 xa = *(const float4*)(X + (size_t)(bm + row) * D_ + k0 + kg);
            bf16 h0, l0, h1, l1, h2, l2, h3, l3;
            split2(xa.x, h0, l0); split2(xa.y, h1, l1);
            split2(xa.z, h2, l2); split2(xa.w, h3, l3);
            Ah[row * GKS + kg + 0] = h0; Al[row * GKS + kg + 0] = l0;
            Ah[row * GKS + kg + 1] = h1; Al[row * GKS + kg + 1] = l1;
            Ah[row * GKS + kg + 2] = h2; Al[row * GKS + kg + 2] = l2;
            Ah[row * GKS + kg + 3] = h3; Al[row * GKS + kg + 3] = l3;
        }
        // B tile 64x32: 512 float4 -> 2/thread
#pragma unroll
        for (int i = 0; i < 2; i++) {
            int idx = t + 256 * i;
            int row = idx >> 3;
            int kg  = (idx & 7) << 2;
            float4 wa = *(const float4*)(W + (size_t)(bn + row) * D_ + k0 + kg);
            bf16 h0, l0, h1, l1, h2, l2, h3, l3;
            split2(wa.x, h0, l0); split2(wa.y, h1, l1);
            split2(wa.z, h2, l2); split2(wa.w, h3, l3);
            Bh[row * GKS + kg + 0] = h0; Bl[row * GKS + kg + 0] = l0;
            Bh[row * GKS + kg + 1] = h1; Bl[row * GKS + kg + 1] = l1;
            Bh[row * GKS + kg + 2] = h2; Bl[row * GKS + kg + 2] = l2;
            Bh[row * GKS + kg + 3] = h3; Bl[row * GKS + kg + 3] = l3;
        }
        __syncthreads();

#pragma unroll
        for (int ks = 0; ks < 2; ks++) {
            const int k = ks * 16;
            FragA  ah, al;
            FragBc bh0, bh1, bl;
            wmma::load_matrix_sync(bh0, Bh + (wn +  0) * GKS + k, GKS);
            wmma::load_matrix_sync(bh1, Bh + (wn + 16) * GKS + k, GKS);

            wmma::load_matrix_sync(ah, Ah + (wm + 0) * GKS + k, GKS);
            wmma::mma_sync(acc00, ah, bh0, acc00);
            wmma::mma_sync(acc01, ah, bh1, acc01);
            wmma::load_matrix_sync(bl, Bl + (wn + 0) * GKS + k, GKS);
            wmma::mma_sync(acc00, ah, bl, acc00);
            wmma::load_matrix_sync(al, Al + (wm + 0) * GKS + k, GKS);
            wmma::mma_sync(acc00, al, bh0, acc00);

            wmma::load_matrix_sync(ah, Ah + (wm + 16) * GKS + k, GKS);
            wmma::mma_sync(acc10, ah, bh0, acc10);
            wmma::mma_sync(acc11, ah, bh1, acc11);
            wmma::mma_sync(acc10, ah, bl, acc10);
            wmma::load_matrix_sync(al, Al + (wm + 16) * GKS + k, GKS);
            wmma::mma_sync(acc10, al, bh0, acc10);

            wmma::load_matrix_sync(bl, Bl + (wn + 16) * GKS + k, GKS);
            wmma::load_matrix_sync(ah, Ah + (wm + 0) * GKS + k, GKS);
            wmma::mma_sync(acc01, ah, bl, acc01);
            wmma::load_matrix_sync(al, Al + (wm + 0) * GKS + k, GKS);
            wmma::mma_sync(acc01, al, bh1, acc01);
            wmma::load_matrix_sync(ah, Ah + (wm + 16) * GKS + k, GKS);
            wmma::mma_sync(acc11, ah, bl, acc11);
            wmma::load_matrix_sync(al, Al + (wm + 16) * GKS + k, GKS);
            wmma::mma_sync(acc11, al, bh1, acc11);
        }
        __syncthreads();
    }

    // epilogue via smem
    wmma::store_matrix_sync(Cs + (wm +  0) * CST + wn +  0, acc00, CST, wmma::mem_row_major);
    wmma::store_matrix_sync(Cs + (wm +  0) * CST + wn + 16, acc01, CST, wmma::mem_row_major);
    wmma::store_matrix_sync(Cs + (wm + 16) * CST + wn +  0, acc10, CST, wmma::mem_row_major);
    wmma::store_matrix_sync(Cs + (wm + 16) * CST + wn + 16, acc11, CST, wmma::mem_row_major);
    __syncthreads();

#pragma unroll
    for (int i = 0; i < 32; i++) {
        int idx = t + 256 * i;
        int row = idx >> 6;
        int col = idx & 63;
        int m = bm + row;
        int n = bn + col;
        float val = Cs[row * CST + col] + bias[n];
        if (mode == 0) {
            int bi = m >> 11, s = m & (S_ - 1);
            int h = n >> 6, dk = n & 63;
            outp[(((size_t)(bi * H_ + h)) * S_ + s) * DK_ + dk] = val;
        } else {
            g_x[(size_t)m * D_ + n] = val + res[(size_t)m * D_ + n];
        }
    }
}

// ===========================================================================
// Flash attention, bf16-split wmma. Bq=64, Bk=64, 8 warps (2m x 4n of 32x16).
// Shift-free softmax (scores bounded: |s|<~3), fp32 row sums, P split hi/lo.
// ===========================================================================
#define FKS 80   // bf16 tile stride (elems): 160B rows
#define SST 72   // fp32 score/out stride

#define OFF_QH 0
#define OFF_QL (OFF_QH + 64*FKS*2)
#define OFF_KH (OFF_QL + 64*FKS*2)
#define OFF_KL (OFF_KH + 64*FKS*2)
#define OFF_VH (OFF_KL + 64*FKS*2)
#define OFF_VL (OFF_VH + 64*FKS*2)
#define OFF_SS (OFF_VL + 64*FKS*2)
#define OFF_PH (OFF_SS + 64*SST*4)
#define OFF_PL (OFF_PH + 64*FKS*2)
#define FLASH_SMEM (OFF_PL + 64*FKS*2)

__global__ void flash_tc(const int* __restrict__ mask)
{
    extern __shared__ __align__(32) char fsm[];
    bf16*  Qh = (bf16*)(fsm + OFF_QH);
    bf16*  Ql = (bf16*)(fsm + OFF_QL);
    bf16*  Kh = (bf16*)(fsm + OFF_KH);
    bf16*  Kl = (bf16*)(fsm + OFF_KL);
    bf16*  Vh = (bf16*)(fsm + OFF_VH);
    bf16*  Vl = (bf16*)(fsm + OFF_VL);
    float* Ss = (float*)(fsm + OFF_SS);
    bf16*  Ph = (bf16*)(fsm + OFF_PH);
    bf16*  Pl = (bf16*)(fsm + OFF_PL);

    const int b  = blockIdx.z;
    const int h  = blockIdx.y;
    const int q0 = blockIdx.x * 64;
    const int t  = threadIdx.x;
    const int w  = t >> 5;
    const int wm = (w & 1) * 32;
    const int wn = (w >> 1) * 16;

    const float* Qg = g_Qh + ((size_t)(b * H_ + h)) * S_ * DK_;
    const float* Kg = g_Kh + ((size_t)(b * H_ + h)) * S_ * DK_;
    const float* Vg = g_Vh + ((size_t)(b * H_ + h)) * S_ * DK_;
    const int* mbase = mask + (size_t)b * S_ * S_;

    // load Q tile 64x64: 4 float4/thread
#pragma unroll
    for (int i = 0; i < 4; i++) {
        int idx = t + 256 * i;
        int row = idx >> 4;
        int dg  = (idx & 15) << 2;
        float4 qa = *(const float4*)(Qg + (size_t)(q0 + row) * DK_ + dg);
        bf16 h0, l0, h1, l1, h2, l2, h3, l3;
        split2(qa.x, h0, l0); split2(qa.y, h1, l1);
        split2(qa.z, h2, l2); split2(qa.w, h3, l3);
        Qh[row * FKS + dg + 0] = h0; Ql[row * FKS + dg + 0] = l0;
        Qh[row * FKS + dg + 1] = h1; Ql[row * FKS + dg + 1] = l1;
        Qh[row * FKS + dg + 2] = h2; Ql[row * FKS + dg + 2] = l2;
        Qh[row * FKS + dg + 3] = h3; Ql[row * FKS + dg + 3] = l3;
    }

    FragC oacc0, oacc1;
    wmma::fill_fragment(oacc0, 0.f);
    wmma::fill_fragment(oacc1, 0.f);

    const int srow = t >> 2;          // softmax row owned (0..63)
    const int scol = (t & 3) * 16;    // 16-col slice
    float lsum = 0.f;

    __syncthreads();

    for (int k0 = 0; k0 < S_; k0 += 64) {
        // load K, V tiles 64x64 each
#pragma unroll
        for (int i = 0; i < 4; i++) {
            int idx = t + 256 * i;
            int row = idx >> 4;
            int dg  = (idx & 15) << 2;
            float4 ka = *(const float4*)(Kg + (size_t)(k0 + row) * DK_ + dg);
            bf16 h0, l0, h1, l1, h2, l2, h3, l3;
            split2(ka.x, h0, l0); split2(ka.y, h1, l1);
            split2(ka.z, h2, l2); split2(ka.w, h3, l3);
            Kh[row * FKS + dg + 0] = h0; Kl[row * FKS + dg + 0] = l0;
            Kh[row * FKS + dg + 1] = h1; Kl[row * FKS + dg + 1] = l1;
            Kh[row * FKS + dg + 2] = h2; Kl[row * FKS + dg + 2] = l2;
            Kh[row * FKS + dg + 3] = h3; Kl[row * FKS + dg + 3] = l3;
            float4 va = *(const float4*)(Vg + (size_t)(k0 + row) * DK_ + dg);
            split2(va.x, h0, l0); split2(va.y, h1, l1);
            split2(va.z, h2, l2); split2(va.w, h3, l3);
            Vh[row * FKS + dg + 0] = h0; Vl[row * FKS + dg + 0] = l0;
            Vh[row * FKS + dg + 1] = h1; Vl[row * FKS + dg + 1] = l1;
            Vh[row * FKS + dg + 2] = h2; Vl[row * FKS + dg + 2] = l2;
            Vh[row * FKS + dg + 3] = h3; Vl[row * FKS + dg + 3] = l3;
        }
        __syncthreads();

        // ---- S = Q @ K^T : warp's 32x16 stripe ----
        {
            FragC sacc0, sacc1;
            wmma::fill_fragment(sacc0, 0.f);
            wmma::fill_fragment(sacc1, 0.f);
#pragma unroll
            for (int ks = 0; ks < 4; ks++) {
                const int k = ks * 16;
                FragA  qa;
                FragBc kh, kl;
                wmma::load_matrix_sync(kh, Kh + wn * FKS + k, FKS);
                wmma::load_matrix_sync(kl, Kl + wn * FKS + k, FKS);
                wmma::load_matrix_sync(qa, Qh + (wm + 0) * FKS + k, FKS);
                wmma::mma_sync(sacc0, qa, kh, sacc0);
                wmma::mma_sync(sacc0, qa, kl, sacc0);
                wmma::load_matrix_sync(qa, Ql + (wm + 0) * FKS + k, FKS);
                wmma::mma_sync(sacc0, qa, kh, sacc0);
                wmma::load_matrix_sync(qa, Qh + (wm + 16) * FKS + k, FKS);
                wmma::mma_sync(sacc1, qa, kh, sacc1);
                wmma::mma_sync(sacc1, qa, kl, sacc1);
                wmma::load_matrix_sync(qa, Ql + (wm + 16) * FKS + k, FKS);
                wmma::mma_sync(sacc1, qa, kh, sacc1);
            }
            wmma::store_matrix_sync(Ss + (wm +  0) * SST + wn, sacc0, SST, wmma::mem_row_major);
            wmma::store_matrix_sync(Ss + (wm + 16) * SST + wn, sacc1, SST, wmma::mem_row_major);
        }
        __syncthreads();

        // ---- shift-free softmax on 16 elems/thread + fp32 row sum ----
        {
            const int grow = q0 + srow;
            const int* mrow = mbase + (size_t)grow * S_ + k0 + scol;
            float part = 0.f;
#pragma unroll
            for (int c = 0; c < 16; c++) {
                float sv = Ss[srow * SST + scol + c] * 0.125f;
                float p = (mrow[c] == 0) ? 0.f : __expf(sv);
                part += p;
                bf16 ph, pl;
                split2(p, ph, pl);
                Ph[srow * FKS + scol + c] = ph;
                Pl[srow * FKS + scol + c] = pl;
            }
            part += __shfl_xor_sync(0xffffffffu, part, 1);
            part += __shfl_xor_sync(0xffffffffu, part, 2);
            lsum += part;
        }
        __syncthreads();

        // ---- O += P @ V : warp's 32x16 stripe ----
#pragma unroll
        for (int ks = 0; ks < 4; ks++) {
            const int k = ks * 16;
            FragA  pa;
            FragBr vh, vl;
            wmma::load_matrix_sync(vh, Vh + k * FKS + wn, FKS);
            wmma::load_matrix_sync(vl, Vl + k * FKS + wn, FKS);
            wmma::load_matrix_sync(pa, Ph + (wm + 0) * FKS + k, FKS);
            wmma::mma_sync(oacc0, pa, vh, oacc0);
            wmma::mma_sync(oacc0, pa, vl, oacc0);
            wmma::load_matrix_sync(pa, Pl + (wm + 0) * FKS + k, FKS);
            wmma::mma_sync(oacc0, pa, vh, oacc0);
            wmma::load_matrix_sync(pa, Ph + (wm + 16) * FKS + k, FKS);
            wmma::mma_sync(oacc1, pa, vh, oacc1);
            wmma::mma_sync(oacc1, pa, vl, oacc1);
            wmma::load_matrix_sync(pa, Pl + (wm + 16) * FKS + k, FKS);
            wmma::mma_sync(oacc1, pa, vh, oacc1);
        }
        __syncthreads();
    }

    // ---- epilogue: O -> smem, normalize, write g_ctx ----
    wmma::store_matrix_sync(Ss + (wm +  0) * SST + wn, oacc0, SST, wmma::mem_row_major);
    wmma::store_matrix_sync(Ss + (wm + 16) * SST + wn, oacc1, SST, wmma::mem_row_major);
    __syncthreads();

    {
        float inv = 1.0f / lsum;
        float* gout = g_ctx + ((size_t)b * S_ + (q0 + srow)) * D_ + h * DK_ + scol;
#pragma unroll
        for (int c = 0; c < 16; c++)
            gout[c] = Ss[srow * SST + scol + c] * inv;
    }
}

// ===========================================================================
// LayerNorm over D=1024 per row
// ===========================================================================
__global__ __launch_bounds__(256) void ln_kernel(const float* __restrict__ gamma,
                                                 const float* __restrict__ beta,
                                                 float* __restrict__ out)
{
    const int row = blockIdx.x;
    const int t   = threadIdx.x;
    const float* x = g_x + (size_t)row * D_;

    float4 v = *(const float4*)(x + t * 4);
    float s  = v.x + v.y + v.z + v.w;
    float ss = v.x * v.x + v.y * v.y + v.z * v.z + v.w * v.w;
#pragma unroll
    for (int off = 16; off >= 1; off >>= 1) {
        s  += __shfl_xor_sync(0xffffffffu, s,  off);
        ss += __shfl_xor_sync(0xffffffffu, ss, off);
    }
    __shared__ float red[8][2];
    int w = t >> 5, ln = t & 31;
    if (ln == 0) { red[w][0] = s; red[w][1] = ss; }
    __syncthreads();
    s = 0.f; ss = 0.f;
#pragma unroll
    for (int i = 0; i < 8; i++) { s += red[i][0]; ss += red[i][1]; }

    float mean = s * (1.0f / D_);
    float var  = ss * (1.0f / D_) - mean * mean;
    float rstd = rsqrtf(var + 1e-5f);

    float4 g  = *(const float4*)(gamma + t * 4);
    float4 be = *(const float4*)(beta + t * 4);
    float4 ov;
    ov.x = (v.x - mean) * rstd * g.x + be.x;
    ov.y = (v.y - mean) * rstd * g.y + be.y;
    ov.z = (v.z - mean) * rstd * g.z + be.z;
    ov.w = (v.w - mean) * rstd * g.w + be.w;
    *(float4*)(out + (size_t)row * D_ + t * 4) = ov;
}

// ===========================================================================
extern "C" void kernel_launch(void* const* d_in, const int* in_sizes, int n_in,
                              void* d_out, int out_size)
{
    const float* q     = (const float*)d_in[0];
    const float* k     = (const float*)d_in[1];
    const float* v     = (const float*)d_in[2];
    const int*   mask  = (const int*)  d_in[3];
    const float* Wq    = (const float*)d_in[4];
    const float* bq    = (const float*)d_in[5];
    const float* Wk    = (const float*)d_in[6];
    const float* bk    = (const float*)d_in[7];
    const float* Wv    = (const float*)d_in[8];
    const float* bv    = (const float*)d_in[9];
    const float* Wo    = (const float*)d_in[10];
    const float* bo    = (const float*)d_in[11];
    const float* gamma = (const float*)d_in[12];
    const float* beta  = (const float*)d_in[13];
    float* out = (float*)d_out;

    dim3 gGemm(D_ / 64, BS_ / 128);        // (16, 32)
    gemm_tc<<<gGemm, 256>>>(q, Wq, bq, nullptr, 0, 0);
    gemm_tc<<<gGemm, 256>>>(k, Wk, bk, nullptr, 0, 1);
    gemm_tc<<<gGemm, 256>>>(v, Wv, bv, nullptr, 0, 2);

    cudaFuncSetAttribute(flash_tc, cudaFuncAttributeMaxDynamicSharedMemorySize, FLASH_SMEM);
    dim3 gFlash(S_ / 64, H_, B_);           // (32, 16, 2)
    flash_tc<<<gFlash, 256, FLASH_SMEM>>>(mask);

    // mode 1: X resolved device-side to g_ctx; host passes nullptr
    gemm_tc<<<gGemm, 256>>>(nullptr, Wo, bo, q, 1, 0);

    ln_kernel<<<BS_, 256>>>(gamma, beta, out);
}

// round 10
// speedup vs baseline: 2.4168x; 2.1506x over previous
#include <cuda_runtime.h>
#include <math.h>

#define B_  2
#define S_  2048
#define D_  1024
#define H_  16
#define DK_ 64
#define BS_ (B_*S_)   // 4096

// ---------------- scratch ----------------
__device__ float g_Qh[B_*H_*S_*DK_];   // [B,H,S,DK]
__device__ float g_Kh[B_*H_*S_*DK_];
__device__ float g_Vh[B_*H_*S_*DK_];
__device__ float g_ctx[BS_*D_];        // concat [B,S,D]
__device__ float g_x[BS_*D_];          // pre-LN (out + residual)

// ---------------- helpers ----------------
__device__ __forceinline__ float tf32r(float x) {
    unsigned u;
    asm("cvt.rna.tf32.f32 %0, %1;" : "=r"(u) : "f"(x));
    return __uint_as_float(u);
}

__device__ __forceinline__ void mma8(float& c0, float& c1, float& c2, float& c3,
                                     unsigned a0, unsigned a1, unsigned a2, unsigned a3,
                                     unsigned b0, unsigned b1) {
    asm volatile(
        "mma.sync.aligned.m16n8k8.row.col.f32.tf32.tf32.f32 "
        "{%0,%1,%2,%3},{%4,%5,%6,%7},{%8,%9},{%0,%1,%2,%3};"
        : "+f"(c0), "+f"(c1), "+f"(c2), "+f"(c3)
        : "r"(a0), "r"(a1), "r"(a2), "r"(a3), "r"(b0), "r"(b1));
}

// ===========================================================================
// tf32 GEMM: C = X @ W^T (+bias [+res]); BM=BN=128, BK=16, 8 warps (64x32 each)
// mode 0: scatter to head layout [B,H,S,DK]  (X = host-provided input)
// mode 1: g_x = C + bias + res               (X := g_ctx, resolved DEVICE-side)
// ===========================================================================
#define GST 136

__global__ __launch_bounds__(256) void gemm_tc(const float* __restrict__ Xin,
                                               const float* __restrict__ W,
                                               const float* __restrict__ bias,
                                               const float* __restrict__ res,
                                               int mode, int which)
{
    __shared__ float As[16 * GST];
    __shared__ float Bs[16 * GST];

    // device-side symbol resolution (NEVER pass __device__ symbols from host)
    const float* X = (mode == 1) ? (const float*)g_ctx : Xin;
    float* outp = (which == 0) ? g_Qh : (which == 1) ? g_Kh : g_Vh;

    const int bm = blockIdx.y * 128;
    const int bn = blockIdx.x * 128;
    const int t    = threadIdx.x;
    const int w    = t >> 5;
    const int lane = t & 31;
    const int gid  = lane >> 2;   // 0..7
    const int tid  = lane & 3;    // 0..3
    const int wm   = (w & 1) * 64;
    const int wn   = (w >> 1) * 32;

    float c[4][4][4];
#pragma unroll
    for (int i = 0; i < 4; i++)
#pragma unroll
        for (int j = 0; j < 4; j++)
#pragma unroll
            for (int r = 0; r < 4; r++) c[i][j][r] = 0.f;

    for (int k0 = 0; k0 < D_; k0 += 16) {
#pragma unroll
        for (int i = 0; i < 2; i++) {
            int l4  = t + 256 * i;          // 0..511
            int row = l4 >> 2;              // 0..127
            int kg  = (l4 & 3) << 2;        // 0,4,8,12
            float4 xa = *(const float4*)(X + (size_t)(bm + row) * D_ + k0 + kg);
            As[(kg + 0) * GST + row] = tf32r(xa.x);
            As[(kg + 1) * GST + row] = tf32r(xa.y);
            As[(kg + 2) * GST + row] = tf32r(xa.z);
            As[(kg + 3) * GST + row] = tf32r(xa.w);
            float4 wa = *(const float4*)(W + (size_t)(bn + row) * D_ + k0 + kg);
            Bs[(kg + 0) * GST + row] = tf32r(wa.x);
            Bs[(kg + 1) * GST + row] = tf32r(wa.y);
            Bs[(kg + 2) * GST + row] = tf32r(wa.z);
            Bs[(kg + 3) * GST + row] = tf32r(wa.w);
        }
        __syncthreads();

#pragma unroll
        for (int ks = 0; ks < 2; ks++) {
            const int k = ks * 8;
            unsigned a0[4], a1[4], a2[4], a3[4], bf0[4], bf1[4];
#pragma unroll
            for (int i = 0; i < 4; i++) {
                int r0 = wm + i * 16 + gid;
                a0[i] = __float_as_uint(As[(k + tid)     * GST + r0]);
                a1[i] = __float_as_uint(As[(k + tid)     * GST + r0 + 8]);
                a2[i] = __float_as_uint(As[(k + tid + 4) * GST + r0]);
                a3[i] = __float_as_uint(As[(k + tid + 4) * GST + r0 + 8]);
            }
#pragma unroll
            for (int j = 0; j < 4; j++) {
                int n0 = wn + j * 8 + gid;
                bf0[j] = __float_as_uint(Bs[(k + tid)     * GST + n0]);
                bf1[j] = __float_as_uint(Bs[(k + tid + 4) * GST + n0]);
            }
#pragma unroll
            for (int i = 0; i < 4; i++)
#pragma unroll
                for (int j = 0; j < 4; j++)
                    mma8(c[i][j][0], c[i][j][1], c[i][j][2], c[i][j][3],
                         a0[i], a1[i], a2[i], a3[i], bf0[j], bf1[j]);
        }
        __syncthreads();
    }

    // epilogue
#pragma unroll
    for (int i = 0; i < 4; i++) {
        int r0 = bm + wm + i * 16 + gid;
        int r1 = r0 + 8;
#pragma unroll
        for (int j = 0; j < 4; j++) {
            int n0 = bn + wn + j * 8 + tid * 2;
            int n1 = n0 + 1;
            if (mode == 0) {
                int b0i = r0 >> 11, s0 = r0 & (S_ - 1);
                int b1i = r1 >> 11, s1 = r1 & (S_ - 1);
                int h0 = n0 >> 6, d0 = n0 & 63;
                int h1 = n1 >> 6, d1 = n1 & 63;
                outp[(((size_t)(b0i * H_ + h0)) * S_ + s0) * DK_ + d0] = c[i][j][0] + bias[n0];
                outp[(((size_t)(b0i * H_ + h1)) * S_ + s0) * DK_ + d1] = c[i][j][1] + bias[n1];
                outp[(((size_t)(b1i * H_ + h0)) * S_ + s1) * DK_ + d0] = c[i][j][2] + bias[n0];
                outp[(((size_t)(b1i * H_ + h1)) * S_ + s1) * DK_ + d1] = c[i][j][3] + bias[n1];
            } else {
                g_x[(size_t)r0 * D_ + n0] = c[i][j][0] + bias[n0] + res[(size_t)r0 * D_ + n0];
                g_x[(size_t)r0 * D_ + n1] = c[i][j][1] + bias[n1] + res[(size_t)r0 * D_ + n1];
                g_x[(size_t)r1 * D_ + n0] = c[i][j][2] + bias[n0] + res[(size_t)r1 * D_ + n0];
                g_x[(size_t)r1 * D_ + n1] = c[i][j][3] + bias[n1] + res[(size_t)r1 * D_ + n1];
            }
        }
    }
}

// ===========================================================================
// Flash attention, tf32 mma. Bq=128 (8 warps x 16 rows), Bk=64.
// smem: Qs[128][68], Ks[64][68], Vs[64][72], Ps[128][68]
// ===========================================================================
#define QST 68
#define VST 72

__global__ __launch_bounds__(256) void flash_tc(const int* __restrict__ mask)
{
    extern __shared__ float sm[];
    float* Qs = sm;                       // 128*68
    float* Ks = Qs + 128 * QST;           // 64*68
    float* Vs = Ks + 64 * QST;            // 64*72
    float* Ps = Vs + 64 * VST;            // 128*68

    const int b  = blockIdx.z;
    const int h  = blockIdx.y;
    const int q0 = blockIdx.x * 128;
    const int t    = threadIdx.x;
    const int w    = t >> 5;
    const int lane = t & 31;
    const int gid  = lane >> 2;
    const int tid  = lane & 3;

    const float* Qg = g_Qh + ((size_t)(b * H_ + h)) * S_ * DK_;
    const float* Kg = g_Kh + ((size_t)(b * H_ + h)) * S_ * DK_;
    const float* Vg = g_Vh + ((size_t)(b * H_ + h)) * S_ * DK_;
    const int* mbase = mask + (size_t)b * S_ * S_;

#pragma unroll
    for (int i = 0; i < 8; i++) {
        int l4  = t + 256 * i;            // 0..2047
        int row = l4 >> 4;                // 0..127
        int dg  = (l4 & 15) << 2;
        float4 qa = *(const float4*)(Qg + (size_t)(q0 + row) * DK_ + dg);
        Qs[row * QST + dg + 0] = tf32r(qa.x);
        Qs[row * QST + dg + 1] = tf32r(qa.y);
        Qs[row * QST + dg + 2] = tf32r(qa.z);
        Qs[row * QST + dg + 3] = tf32r(qa.w);
    }

    float o[8][4];
#pragma unroll
    for (int j = 0; j < 8; j++)
#pragma unroll
        for (int r = 0; r < 4; r++) o[j][r] = 0.f;
    float mprev0 = -1e30f, mprev1 = -1e30f, lsum0 = 0.f, lsum1 = 0.f;

    const int rloc0 = w * 16 + gid;       // local q-row
    const int rloc1 = rloc0 + 8;

    __syncthreads();

    for (int k0 = 0; k0 < S_; k0 += 64) {
#pragma unroll
        for (int i = 0; i < 4; i++) {
            int l4  = t + 256 * i;        // 0..1023
            int row = l4 >> 4;            // 0..63
            int dg  = (l4 & 15) << 2;
            float4 ka = *(const float4*)(Kg + (size_t)(k0 + row) * DK_ + dg);
            Ks[row * QST + dg + 0] = tf32r(ka.x);
            Ks[row * QST + dg + 1] = tf32r(ka.y);
            Ks[row * QST + dg + 2] = tf32r(ka.z);
            Ks[row * QST + dg + 3] = tf32r(ka.w);
            float4 va = *(const float4*)(Vg + (size_t)(k0 + row) * DK_ + dg);
            Vs[row * VST + dg + 0] = tf32r(va.x);
            Vs[row * VST + dg + 1] = tf32r(va.y);
            Vs[row * VST + dg + 2] = tf32r(va.z);
            Vs[row * VST + dg + 3] = tf32r(va.w);
        }
        __syncthreads();

        // ---- S = Q @ K^T ----
        float s[8][4];
#pragma unroll
        for (int j = 0; j < 8; j++)
#pragma unroll
            for (int r = 0; r < 4; r++) s[j][r] = 0.f;

#pragma unroll
        for (int kk = 0; kk < 8; kk++) {
            const int k = kk * 8;
            unsigned qa0 = __float_as_uint(Qs[rloc0 * QST + k + tid]);
            unsigned qa1 = __float_as_uint(Qs[rloc1 * QST + k + tid]);
            unsigned qa2 = __float_as_uint(Qs[rloc0 * QST + k + tid + 4]);
            unsigned qa3 = __float_as_uint(Qs[rloc1 * QST + k + tid + 4]);
#pragma unroll
            for (int j = 0; j < 8; j++) {
                unsigned b0 = __float_as_uint(Ks[(j * 8 + gid) * QST + k + tid]);
                unsigned b1 = __float_as_uint(Ks[(j * 8 + gid) * QST + k + tid + 4]);
                mma8(s[j][0], s[j][1], s[j][2], s[j][3], qa0, qa1, qa2, qa3, b0, b1);
            }
        }

        // ---- scale + mask + online softmax ----
        const float scale = 0.125f;
        const int gr0 = q0 + rloc0;
        const int gr1 = q0 + rloc1;
        float mx0 = -1e30f, mx1 = -1e30f;
#pragma unroll
        for (int j = 0; j < 8; j++) {
            int col = k0 + j * 8 + tid * 2;
            const int* m0p = mbase + (size_t)gr0 * S_ + col;
            const int* m1p = mbase + (size_t)gr1 * S_ + col;
            s[j][0] = (m0p[0] == 0) ? -1e9f : s[j][0] * scale;
            s[j][1] = (m0p[1] == 0) ? -1e9f : s[j][1] * scale;
            s[j][2] = (m1p[0] == 0) ? -1e9f : s[j][2] * scale;
            s[j][3] = (m1p[1] == 0) ? -1e9f : s[j][3] * scale;
            mx0 = fmaxf(mx0, fmaxf(s[j][0], s[j][1]));
            mx1 = fmaxf(mx1, fmaxf(s[j][2], s[j][3]));
        }
#pragma unroll
        for (int off = 1; off <= 2; off <<= 1) {
            mx0 = fmaxf(mx0, __shfl_xor_sync(0xffffffffu, mx0, off));
            mx1 = fmaxf(mx1, __shfl_xor_sync(0xffffffffu, mx1, off));
        }
        float mn0 = fmaxf(mprev0, mx0);
        float mn1 = fmaxf(mprev1, mx1);
        float f0 = __expf(mprev0 - mn0);
        float f1 = __expf(mprev1 - mn1);
        float rs0 = 0.f, rs1 = 0.f;
#pragma unroll
        for (int j = 0; j < 8; j++) {
            s[j][0] = __expf(s[j][0] - mn0);
            s[j][1] = __expf(s[j][1] - mn0);
            s[j][2] = __expf(s[j][2] - mn1);
            s[j][3] = __expf(s[j][3] - mn1);
            rs0 += s[j][0] + s[j][1];
            rs1 += s[j][2] + s[j][3];
            int pc = j * 8 + tid * 2;
            Ps[rloc0 * QST + pc + 0] = tf32r(s[j][0]);
            Ps[rloc0 * QST + pc + 1] = tf32r(s[j][1]);
            Ps[rloc1 * QST + pc + 0] = tf32r(s[j][2]);
            Ps[rloc1 * QST + pc + 1] = tf32r(s[j][3]);
        }
#pragma unroll
        for (int off = 1; off <= 2; off <<= 1) {
            rs0 += __shfl_xor_sync(0xffffffffu, rs0, off);
            rs1 += __shfl_xor_sync(0xffffffffu, rs1, off);
        }
        lsum0 = lsum0 * f0 + rs0;
        lsum1 = lsum1 * f1 + rs1;
        mprev0 = mn0;
        mprev1 = mn1;
#pragma unroll
        for (int j = 0; j < 8; j++) {
            o[j][0] *= f0; o[j][1] *= f0;
            o[j][2] *= f1; o[j][3] *= f1;
        }
        __syncthreads();   // P visible to all

        // ---- O += P @ V ----
#pragma unroll
        for (int kk = 0; kk < 8; kk++) {
            const int k = kk * 8;
            unsigned pa0 = __float_as_uint(Ps[rloc0 * QST + k + tid]);
            unsigned pa1 = __float_as_uint(Ps[rloc1 * QST + k + tid]);
            unsigned pa2 = __float_as_uint(Ps[rloc0 * QST + k + tid + 4]);
            unsigned pa3 = __float_as_uint(Ps[rloc1 * QST + k + tid + 4]);
#pragma unroll
            for (int j = 0; j < 8; j++) {
                unsigned b0 = __float_as_uint(Vs[(k + tid)     * VST + j * 8 + gid]);
                unsigned b1 = __float_as_uint(Vs[(k + tid + 4) * VST + j * 8 + gid]);
                mma8(o[j][0], o[j][1], o[j][2], o[j][3], pa0, pa1, pa2, pa3, b0, b1);
            }
        }
        __syncthreads();   // done with K/V/P before next tile
    }

    // epilogue -> g_ctx [B,S,D] concat layout
    float inv0 = 1.0f / lsum0;
    float inv1 = 1.0f / lsum1;
    float* out0 = g_ctx + ((size_t)b * S_ + (q0 + rloc0)) * D_ + h * DK_;
    float* out1 = g_ctx + ((size_t)b * S_ + (q0 + rloc1)) * D_ + h * DK_;
#pragma unroll
    for (int j = 0; j < 8; j++) {
        int col = j * 8 + tid * 2;
        out0[col + 0] = o[j][0] * inv0;
        out0[col + 1] = o[j][1] * inv0;
        out1[col + 0] = o[j][2] * inv1;
        out1[col + 1] = o[j][3] * inv1;
    }
}

// ===========================================================================
// LayerNorm over D=1024 per row
// ===========================================================================
__global__ __launch_bounds__(256) void ln_kernel(const float* __restrict__ gamma,
                                                 const float* __restrict__ beta,
                                                 float* __restrict__ out)
{
    const int row = blockIdx.x;
    const int t   = threadIdx.x;
    const float* x = g_x + (size_t)row * D_;

    float4 v = *(const float4*)(x + t * 4);
    float s  = v.x + v.y + v.z + v.w;
    float ss = v.x * v.x + v.y * v.y + v.z * v.z + v.w * v.w;
#pragma unroll
    for (int off = 16; off >= 1; off >>= 1) {
        s  += __shfl_xor_sync(0xffffffffu, s,  off);
        ss += __shfl_xor_sync(0xffffffffu, ss, off);
    }
    __shared__ float red[8][2];
    int w = t >> 5, ln = t & 31;
    if (ln == 0) { red[w][0] = s; red[w][1] = ss; }
    __syncthreads();
    s = 0.f; ss = 0.f;
#pragma unroll
    for (int i = 0; i < 8; i++) { s += red[i][0]; ss += red[i][1]; }

    float mean = s * (1.0f / D_);
    float var  = ss * (1.0f / D_) - mean * mean;
    float rstd = rsqrtf(var + 1e-5f);

    float4 g  = *(const float4*)(gamma + t * 4);
    float4 be = *(const float4*)(beta + t * 4);
    float4 ov;
    ov.x = (v.x - mean) * rstd * g.x + be.x;
    ov.y = (v.y - mean) * rstd * g.y + be.y;
    ov.z = (v.z - mean) * rstd * g.z + be.z;
    ov.w = (v.w - mean) * rstd * g.w + be.w;
    *(float4*)(out + (size_t)row * D_ + t * 4) = ov;
}

// ===========================================================================
extern "C" void kernel_launch(void* const* d_in, const int* in_sizes, int n_in,
                              void* d_out, int out_size)
{
    const float* q     = (const float*)d_in[0];
    const float* k     = (const float*)d_in[1];
    const float* v     = (const float*)d_in[2];
    const int*   mask  = (const int*)  d_in[3];
    const float* Wq    = (const float*)d_in[4];
    const float* bq    = (const float*)d_in[5];
    const float* Wk    = (const float*)d_in[6];
    const float* bk    = (const float*)d_in[7];
    const float* Wv    = (const float*)d_in[8];
    const float* bv    = (const float*)d_in[9];
    const float* Wo    = (const float*)d_in[10];
    const float* bo    = (const float*)d_in[11];
    const float* gamma = (const float*)d_in[12];
    const float* beta  = (const float*)d_in[13];
    float* out = (float*)d_out;

    dim3 gGemm(D_ / 128, BS_ / 128);       // (8, 32)
    gemm_tc<<<gGemm, 256>>>(q, Wq, bq, nullptr, 0, 0);
    gemm_tc<<<gGemm, 256>>>(k, Wk, bk, nullptr, 0, 1);
    gemm_tc<<<gGemm, 256>>>(v, Wv, bv, nullptr, 0, 2);

    int smem = (128 * QST + 64 * QST + 64 * VST + 128 * QST) * (int)sizeof(float);
    cudaFuncSetAttribute(flash_tc, cudaFuncAttributeMaxDynamicSharedMemorySize, smem);
    dim3 gFlash(S_ / 128, H_, B_);          // (16, 16, 2)
    flash_tc<<<gFlash, 256, smem>>>(mask);

    // mode 1: X resolved device-side to g_ctx; host passes nullptr
    gemm_tc<<<gGemm, 256>>>(nullptr, Wo, bo, q, 1, 0);

    ln_kernel<<<BS_, 256>>>(gamma, beta, out);
}

// round 11
// speedup vs baseline: 3.3771x; 1.3973x over previous
#include <cuda_runtime.h>
#include <math.h>

#define B_  2
#define S_  2048
#define D_  1024
#define H_  16
#define DK_ 64
#define BS_ (B_*S_)   // 4096

// ---------------- scratch ----------------
__device__ float g_Qh[B_*H_*S_*DK_];   // [B,H,S,DK] (tf32-rounded)
__device__ float g_Kh[B_*H_*S_*DK_];
__device__ float g_Vh[B_*H_*S_*DK_];
__device__ float g_ctx[BS_*D_];        // concat [B,S,D] (tf32-rounded)
__device__ float g_x[BS_*D_];          // pre-LN (full fp32)
__device__ float g_rW[4][D_*D_];       // tf32-rounded weights (q,k,v,o)
__device__ float g_rX[3][BS_*D_];      // tf32-rounded inputs (q,k,v)
__device__ int   g_mflag[B_*16*32];    // per (b, qtile128, ktile64): any mask zero?

// ---------------- helpers ----------------
__device__ __forceinline__ float tf32r(float x) {
    unsigned u;
    asm("cvt.rna.tf32.f32 %0, %1;" : "=r"(u) : "f"(x));
    return __uint_as_float(u);
}

__device__ __forceinline__ void mma8(float& c0, float& c1, float& c2, float& c3,
                                     unsigned a0, unsigned a1, unsigned a2, unsigned a3,
                                     unsigned b0, unsigned b1) {
    asm volatile(
        "mma.sync.aligned.m16n8k8.row.col.f32.tf32.tf32.f32 "
        "{%0,%1,%2,%3},{%4,%5,%6,%7},{%8,%9},{%0,%1,%2,%3};"
        : "+f"(c0), "+f"(c1), "+f"(c2), "+f"(c3)
        : "r"(a0), "r"(a1), "r"(a2), "r"(a3), "r"(b0), "r"(b1));
}

__device__ __forceinline__ void cpasync16(unsigned dst, const void* src) {
    asm volatile("cp.async.cg.shared.global [%0], [%1], 16;" :: "r"(dst), "l"(src));
}
#define CP_COMMIT() asm volatile("cp.async.commit_group;")
#define CP_WAIT1()  asm volatile("cp.async.wait_group 1;")
#define CP_WAIT0()  asm volatile("cp.async.wait_group 0;")

// ===========================================================================
// Prep: tf32-round inputs/weights once.  isW=1 -> g_rW[which], else g_rX[which]
// ===========================================================================
__global__ void prep_cvt(const float* __restrict__ src, int n4, int which, int isW)
{
    float* dst = isW ? g_rW[which] : g_rX[which];
    int i = blockIdx.x * 256 + threadIdx.x;
    if (i < n4) {
        float4 v = *(const float4*)(src + (size_t)i * 4);
        float4 o;
        o.x = tf32r(v.x); o.y = tf32r(v.y); o.z = tf32r(v.z); o.w = tf32r(v.w);
        *(float4*)(dst + (size_t)i * 4) = o;
    }
}

// ===========================================================================
// Mask summary: flag per (b, qtile 128, ktile 64) whether any zero present
// ===========================================================================
__global__ void maskflag_kernel(const int* __restrict__ mask)
{
    const int kt = blockIdx.x, qt = blockIdx.y, b = blockIdx.z;
    const int* mb = mask + ((size_t)b * S_ + qt * 128) * S_ + kt * 64;
    const int t = threadIdx.x;
    int anyz = 0;
#pragma unroll
    for (int i = 0; i < 8; i++) {
        int lin = t + 256 * i;            // 0..2047
        int row = lin >> 4;               // 0..127
        int c4  = (lin & 15) * 4;
        int4 v = *(const int4*)(mb + (size_t)row * S_ + c4);
        anyz |= (v.x == 0) | (v.y == 0) | (v.z == 0) | (v.w == 0);
    }
    anyz = __syncthreads_or(anyz);
    if (t == 0) g_mflag[(b * 16 + qt) * 32 + kt] = anyz;
}

// ===========================================================================
// tf32 GEMM, cp.async 2-stage, BM=BN=128, BK=32, 8 warps (64x32 each).
// Operands pre-rounded (g_rX/g_rW/g_ctx).  [m][36] smem layout.
// mode 0: scatter tf32r(C+bias) to head layout [B,H,S,DK] into g_Q/K/Vh
// mode 1: g_x = C + bias + res (fp32)
// ===========================================================================
#define GAST 36
#define GEMM_STAGE_FLOATS (128*GAST*2)     // A + B per stage = 9216
#define GEMM_SMEM (2*GEMM_STAGE_FLOATS*4)  // 73728 bytes

__global__ __launch_bounds__(256) void gemm_tc(const float* __restrict__ bias,
                                               const float* __restrict__ res,
                                               int mode, int which)
{
    extern __shared__ float gsm[];

    const float* X = (mode == 1) ? (const float*)g_ctx : (const float*)g_rX[which];
    const float* W = (mode == 1) ? (const float*)g_rW[3] : (const float*)g_rW[which];
    float* outp = (which == 0) ? g_Qh : (which == 1) ? g_Kh : g_Vh;

    const int bm = blockIdx.y * 128;
    const int bn = blockIdx.x * 128;
    const int t    = threadIdx.x;
    const int w    = t >> 5;
    const int lane = t & 31;
    const int gid  = lane >> 2;
    const int tid  = lane & 3;
    const int wm   = (w & 1) * 64;
    const int wn   = (w >> 1) * 32;

    const unsigned smaddr = (unsigned)__cvta_generic_to_shared(gsm);

    float c[4][4][4];
#pragma unroll
    for (int i = 0; i < 4; i++)
#pragma unroll
        for (int j = 0; j < 4; j++)
#pragma unroll
            for (int r = 0; r < 4; r++) c[i][j][r] = 0.f;

    // prefetch stage 0
    {
        unsigned ab = smaddr;
        unsigned bb = ab + 128 * GAST * 4;
#pragma unroll
        for (int i = 0; i < 4; i++) {
            int idx = t + 256 * i;
            int row = idx >> 3;
            int c4  = (idx & 7) << 2;
            cpasync16(ab + (row * GAST + c4) * 4, X + (size_t)(bm + row) * D_ + c4);
            cpasync16(bb + (row * GAST + c4) * 4, W + (size_t)(bn + row) * D_ + c4);
        }
        CP_COMMIT();
    }

    for (int it = 0; it < D_ / 32; it++) {
        const int cur = it & 1;
        if (it + 1 < D_ / 32) {
            const int k0 = (it + 1) * 32;
            unsigned ab = smaddr + (cur ^ 1) * GEMM_STAGE_FLOATS * 4;
            unsigned bb = ab + 128 * GAST * 4;
#pragma unroll
            for (int i = 0; i < 4; i++) {
                int idx = t + 256 * i;
                int row = idx >> 3;
                int c4  = (idx & 7) << 2;
                cpasync16(ab + (row * GAST + c4) * 4, X + (size_t)(bm + row) * D_ + k0 + c4);
                cpasync16(bb + (row * GAST + c4) * 4, W + (size_t)(bn + row) * D_ + k0 + c4);
            }
            CP_COMMIT();
            CP_WAIT1();
        } else {
            CP_WAIT0();
        }
        __syncthreads();

        const float* Ab = gsm + cur * GEMM_STAGE_FLOATS;
        const float* Bb = Ab + 128 * GAST;

#pragma unroll
        for (int ks = 0; ks < 4; ks++) {
            const int k = ks * 8;
            unsigned a0[4], a1[4], a2[4], a3[4], bf0[4], bf1[4];
#pragma unroll
            for (int i = 0; i < 4; i++) {
                int r0 = wm + i * 16 + gid;
                a0[i] = __float_as_uint(Ab[(r0    ) * GAST + k + tid]);
                a1[i] = __float_as_uint(Ab[(r0 + 8) * GAST + k + tid]);
                a2[i] = __float_as_uint(Ab[(r0    ) * GAST + k + tid + 4]);
                a3[i] = __float_as_uint(Ab[(r0 + 8) * GAST + k + tid + 4]);
            }
#pragma unroll
            for (int j = 0; j < 4; j++) {
                int n0 = wn + j * 8 + gid;
                bf0[j] = __float_as_uint(Bb[n0 * GAST + k + tid]);
                bf1[j] = __float_as_uint(Bb[n0 * GAST + k + tid + 4]);
            }
#pragma unroll
            for (int i = 0; i < 4; i++)
#pragma unroll
                for (int j = 0; j < 4; j++)
                    mma8(c[i][j][0], c[i][j][1], c[i][j][2], c[i][j][3],
                         a0[i], a1[i], a2[i], a3[i], bf0[j], bf1[j]);
        }
        __syncthreads();
    }

    // epilogue
#pragma unroll
    for (int i = 0; i < 4; i++) {
        int r0 = bm + wm + i * 16 + gid;
        int r1 = r0 + 8;
#pragma unroll
        for (int j = 0; j < 4; j++) {
            int n0 = bn + wn + j * 8 + tid * 2;
            int n1 = n0 + 1;
            if (mode == 0) {
                int b0i = r0 >> 11, s0 = r0 & (S_ - 1);
                int b1i = r1 >> 11, s1 = r1 & (S_ - 1);
                int h0 = n0 >> 6, d0 = n0 & 63;
                int h1 = n1 >> 6, d1 = n1 & 63;
                outp[(((size_t)(b0i * H_ + h0)) * S_ + s0) * DK_ + d0] = tf32r(c[i][j][0] + bias[n0]);
                outp[(((size_t)(b0i * H_ + h1)) * S_ + s0) * DK_ + d1] = tf32r(c[i][j][1] + bias[n1]);
                outp[(((size_t)(b1i * H_ + h0)) * S_ + s1) * DK_ + d0] = tf32r(c[i][j][2] + bias[n0]);
                outp[(((size_t)(b1i * H_ + h1)) * S_ + s1) * DK_ + d1] = tf32r(c[i][j][3] + bias[n1]);
            } else {
                g_x[(size_t)r0 * D_ + n0] = c[i][j][0] + bias[n0] + res[(size_t)r0 * D_ + n0];
                g_x[(size_t)r0 * D_ + n1] = c[i][j][1] + bias[n1] + res[(size_t)r0 * D_ + n1];
                g_x[(size_t)r1 * D_ + n0] = c[i][j][2] + bias[n0] + res[(size_t)r1 * D_ + n0];
                g_x[(size_t)r1 * D_ + n1] = c[i][j][3] + bias[n1] + res[(size_t)r1 * D_ + n1];
            }
        }
    }
}

// ===========================================================================
// Flash attention, tf32 mma. Bq=128 (8 warps x 16 rows), Bk=64.
// Inputs pre-rounded; mask handled via per-tile flags (fast path skips loads).
// ===========================================================================
#define QST 68
#define VST 72

__global__ __launch_bounds__(256) void flash_tc(const int* __restrict__ mask)
{
    extern __shared__ float sm[];
    float* Qs = sm;                       // 128*68
    float* Ks = Qs + 128 * QST;           // 64*68
    float* Vs = Ks + 64 * QST;            // 64*72
    float* Ps = Vs + 64 * VST;            // 128*68

    const int b  = blockIdx.z;
    const int h  = blockIdx.y;
    const int q0 = blockIdx.x * 128;
    const int t    = threadIdx.x;
    const int w    = t >> 5;
    const int lane = t & 31;
    const int gid  = lane >> 2;
    const int tid  = lane & 3;

    const float* Qg = g_Qh + ((size_t)(b * H_ + h)) * S_ * DK_;
    const float* Kg = g_Kh + ((size_t)(b * H_ + h)) * S_ * DK_;
    const float* Vg = g_Vh + ((size_t)(b * H_ + h)) * S_ * DK_;
    const int* mbase = mask + (size_t)b * S_ * S_;
    const int* mflag = g_mflag + (b * 16 + blockIdx.x) * 32;

    // load Q tile (pre-rounded): pure float4 copies
#pragma unroll
    for (int i = 0; i < 8; i++) {
        int l4  = t + 256 * i;
        int row = l4 >> 4;
        int dg  = (l4 & 15) << 2;
        *(float4*)(Qs + row * QST + dg) = *(const float4*)(Qg + (size_t)(q0 + row) * DK_ + dg);
    }

    float o[8][4];
#pragma unroll
    for (int j = 0; j < 8; j++)
#pragma unroll
        for (int r = 0; r < 4; r++) o[j][r] = 0.f;
    float mprev0 = -1e30f, mprev1 = -1e30f, lsum0 = 0.f, lsum1 = 0.f;

    const int rloc0 = w * 16 + gid;
    const int rloc1 = rloc0 + 8;

    __syncthreads();

    for (int k0 = 0; k0 < S_; k0 += 64) {
#pragma unroll
        for (int i = 0; i < 4; i++) {
            int l4  = t + 256 * i;
            int row = l4 >> 4;
            int dg  = (l4 & 15) << 2;
            *(float4*)(Ks + row * QST + dg) = *(const float4*)(Kg + (size_t)(k0 + row) * DK_ + dg);
            *(float4*)(Vs + row * VST + dg) = *(const float4*)(Vg + (size_t)(k0 + row) * DK_ + dg);
        }
        __syncthreads();

        // ---- S = Q @ K^T ----
        float s[8][4];
#pragma unroll
        for (int j = 0; j < 8; j++)
#pragma unroll
            for (int r = 0; r < 4; r++) s[j][r] = 0.f;

#pragma unroll
        for (int kk = 0; kk < 8; kk++) {
            const int k = kk * 8;
            unsigned qa0 = __float_as_uint(Qs[rloc0 * QST + k + tid]);
            unsigned qa1 = __float_as_uint(Qs[rloc1 * QST + k + tid]);
            unsigned qa2 = __float_as_uint(Qs[rloc0 * QST + k + tid + 4]);
            unsigned qa3 = __float_as_uint(Qs[rloc1 * QST + k + tid + 4]);
#pragma unroll
            for (int j = 0; j < 8; j++) {
                unsigned b0 = __float_as_uint(Ks[(j * 8 + gid) * QST + k + tid]);
                unsigned b1 = __float_as_uint(Ks[(j * 8 + gid) * QST + k + tid + 4]);
                mma8(s[j][0], s[j][1], s[j][2], s[j][3], qa0, qa1, qa2, qa3, b0, b1);
            }
        }

        // ---- scale (+mask only if tile has zeros) ----
        const float scale = 0.125f;
#pragma unroll
        for (int j = 0; j < 8; j++) {
            s[j][0] *= scale; s[j][1] *= scale;
            s[j][2] *= scale; s[j][3] *= scale;
        }
        if (mflag[k0 >> 6]) {
            const int gr0 = q0 + rloc0;
            const int gr1 = q0 + rloc1;
#pragma unroll
            for (int j = 0; j < 8; j++) {
                int col = k0 + j * 8 + tid * 2;
                const int* m0p = mbase + (size_t)gr0 * S_ + col;
                const int* m1p = mbase + (size_t)gr1 * S_ + col;
                if (m0p[0] == 0) s[j][0] = -1e9f;
                if (m0p[1] == 0) s[j][1] = -1e9f;
                if (m1p[0] == 0) s[j][2] = -1e9f;
                if (m1p[1] == 0) s[j][3] = -1e9f;
            }
        }

        // ---- online softmax ----
        float mx0 = -1e30f, mx1 = -1e30f;
#pragma unroll
        for (int j = 0; j < 8; j++) {
            mx0 = fmaxf(mx0, fmaxf(s[j][0], s[j][1]));
            mx1 = fmaxf(mx1, fmaxf(s[j][2], s[j][3]));
        }
#pragma unroll
        for (int off = 1; off <= 2; off <<= 1) {
            mx0 = fmaxf(mx0, __shfl_xor_sync(0xffffffffu, mx0, off));
            mx1 = fmaxf(mx1, __shfl_xor_sync(0xffffffffu, mx1, off));
        }
        float mn0 = fmaxf(mprev0, mx0);
        float mn1 = fmaxf(mprev1, mx1);
        float f0 = __expf(mprev0 - mn0);
        float f1 = __expf(mprev1 - mn1);
        float rs0 = 0.f, rs1 = 0.f;
#pragma unroll
        for (int j = 0; j < 8; j++) {
            s[j][0] = __expf(s[j][0] - mn0);
            s[j][1] = __expf(s[j][1] - mn0);
            s[j][2] = __expf(s[j][2] - mn1);
            s[j][3] = __expf(s[j][3] - mn1);
            rs0 += s[j][0] + s[j][1];
            rs1 += s[j][2] + s[j][3];
            int pc = j * 8 + tid * 2;
            *(float2*)(Ps + rloc0 * QST + pc) = make_float2(tf32r(s[j][0]), tf32r(s[j][1]));
            *(float2*)(Ps + rloc1 * QST + pc) = make_float2(tf32r(s[j][2]), tf32r(s[j][3]));
        }
#pragma unroll
        for (int off = 1; off <= 2; off <<= 1) {
            rs0 += __shfl_xor_sync(0xffffffffu, rs0, off);
            rs1 += __shfl_xor_sync(0xffffffffu, rs1, off);
        }
        lsum0 = lsum0 * f0 + rs0;
        lsum1 = lsum1 * f1 + rs1;
        mprev0 = mn0;
        mprev1 = mn1;
#pragma unroll
        for (int j = 0; j < 8; j++) {
            o[j][0] *= f0; o[j][1] *= f0;
            o[j][2] *= f1; o[j][3] *= f1;
        }
        __syncthreads();   // P visible to all

        // ---- O += P @ V ----
#pragma unroll
        for (int kk = 0; kk < 8; kk++) {
            const int k = kk * 8;
            unsigned pa0 = __float_as_uint(Ps[rloc0 * QST + k + tid]);
            unsigned pa1 = __float_as_uint(Ps[rloc1 * QST + k + tid]);
            unsigned pa2 = __float_as_uint(Ps[rloc0 * QST + k + tid + 4]);
            unsigned pa3 = __float_as_uint(Ps[rloc1 * QST + k + tid + 4]);
#pragma unroll
            for (int j = 0; j < 8; j++) {
                unsigned b0 = __float_as_uint(Vs[(k + tid)     * VST + j * 8 + gid]);
                unsigned b1 = __float_as_uint(Vs[(k + tid + 4) * VST + j * 8 + gid]);
                mma8(o[j][0], o[j][1], o[j][2], o[j][3], pa0, pa1, pa2, pa3, b0, b1);
            }
        }
        __syncthreads();
    }

    // epilogue -> g_ctx (tf32-rounded; it feeds the out-proj mma)
    float inv0 = 1.0f / lsum0;
    float inv1 = 1.0f / lsum1;
    float* out0 = g_ctx + ((size_t)b * S_ + (q0 + rloc0)) * D_ + h * DK_;
    float* out1 = g_ctx + ((size_t)b * S_ + (q0 + rloc1)) * D_ + h * DK_;
#pragma unroll
    for (int j = 0; j < 8; j++) {
        int col = j * 8 + tid * 2;
        out0[col + 0] = tf32r(o[j][0] * inv0);
        out0[col + 1] = tf32r(o[j][1] * inv0);
        out1[col + 0] = tf32r(o[j][2] * inv1);
        out1[col + 1] = tf32r(o[j][3] * inv1);
    }
}

// ===========================================================================
// LayerNorm over D=1024 per row
// ===========================================================================
__global__ __launch_bounds__(256) void ln_kernel(const float* __restrict__ gamma,
                                                 const float* __restrict__ beta,
                                                 float* __restrict__ out)
{
    const int row = blockIdx.x;
    const int t   = threadIdx.x;
    const float* x = g_x + (size_t)row * D_;

    float4 v = *(const float4*)(x + t * 4);
    float s  = v.x + v.y + v.z + v.w;
    float ss = v.x * v.x + v.y * v.y + v.z * v.z + v.w * v.w;
#pragma unroll
    for (int off = 16; off >= 1; off >>= 1) {
        s  += __shfl_xor_sync(0xffffffffu, s,  off);
        ss += __shfl_xor_sync(0xffffffffu, ss, off);
    }
    __shared__ float red[8][2];
    int w = t >> 5, ln = t & 31;
    if (ln == 0) { red[w][0] = s; red[w][1] = ss; }
    __syncthreads();
    s = 0.f; ss = 0.f;
#pragma unroll
    for (int i = 0; i < 8; i++) { s += red[i][0]; ss += red[i][1]; }

    float mean = s * (1.0f / D_);
    float var  = ss * (1.0f / D_) - mean * mean;
    float rstd = rsqrtf(var + 1e-5f);

    float4 g  = *(const float4*)(gamma + t * 4);
    float4 be = *(const float4*)(beta + t * 4);
    float4 ov;
    ov.x = (v.x - mean) * rstd * g.x + be.x;
    ov.y = (v.y - mean) * rstd * g.y + be.y;
    ov.z = (v.z - mean) * rstd * g.z + be.z;
    ov.w = (v.w - mean) * rstd * g.w + be.w;
    *(float4*)(out + (size_t)row * D_ + t * 4) = ov;
}

// ===========================================================================
extern "C" void kernel_launch(void* const* d_in, const int* in_sizes, int n_in,
                              void* d_out, int out_size)
{
    const float* q     = (const float*)d_in[0];
    const float* k     = (const float*)d_in[1];
    const float* v     = (const float*)d_in[2];
    const int*   mask  = (const int*)  d_in[3];
    const float* Wq    = (const float*)d_in[4];
    const float* bq    = (const float*)d_in[5];
    const float* Wk    = (const float*)d_in[6];
    const float* bk    = (const float*)d_in[7];
    const float* Wv    = (const float*)d_in[8];
    const float* bv    = (const float*)d_in[9];
    const float* Wo    = (const float*)d_in[10];
    const float* bo    = (const float*)d_in[11];
    const float* gamma = (const float*)d_in[12];
    const float* beta  = (const float*)d_in[13];
    float* out = (float*)d_out;

    // prep: tf32-round inputs and weights (device-side symbol selection)
    const int nX4 = BS_ * D_ / 4;   // 1048576
    const int nW4 = D_ * D_ / 4;    // 262144
    prep_cvt<<<(nX4 + 255) / 256, 256>>>(q,  nX4, 0, 0);
    prep_cvt<<<(nX4 + 255) / 256, 256>>>(k,  nX4, 1, 0);
    prep_cvt<<<(nX4 + 255) / 256, 256>>>(v,  nX4, 2, 0);
    prep_cvt<<<(nW4 + 255) / 256, 256>>>(Wq, nW4, 0, 1);
    prep_cvt<<<(nW4 + 255) / 256, 256>>>(Wk, nW4, 1, 1);
    prep_cvt<<<(nW4 + 255) / 256, 256>>>(Wv, nW4, 2, 1);
    prep_cvt<<<(nW4 + 255) / 256, 256>>>(Wo, nW4, 3, 1);

    // mask tile flags
    maskflag_kernel<<<dim3(32, 16, B_), 256>>>(mask);

    cudaFuncSetAttribute(gemm_tc, cudaFuncAttributeMaxDynamicSharedMemorySize, GEMM_SMEM);
    dim3 gGemm(D_ / 128, BS_ / 128);       // (8, 32)
    gemm_tc<<<gGemm, 256, GEMM_SMEM>>>(bq, nullptr, 0, 0);
    gemm_tc<<<gGemm, 256, GEMM_SMEM>>>(bk, nullptr, 0, 1);
    gemm_tc<<<gGemm, 256, GEMM_SMEM>>>(bv, nullptr, 0, 2);

    int smem = (128 * QST + 64 * QST + 64 * VST + 128 * QST) * (int)sizeof(float);
    cudaFuncSetAttribute(flash_tc, cudaFuncAttributeMaxDynamicSharedMemorySize, smem);
    dim3 gFlash(S_ / 128, H_, B_);          // (16, 16, 2)
    flash_tc<<<gFlash, 256, smem>>>(mask);

    gemm_tc<<<gGemm, 256, GEMM_SMEM>>>(bo, q, 1, 0);

    ln_kernel<<<BS_, 256>>>(gamma, beta, out);
}

// round 12
// speedup vs baseline: 3.4883x; 1.0329x over previous
#include <cuda_runtime.h>
#include <math.h>

#define B_  2
#define S_  2048
#define D_  1024
#define H_  16
#define DK_ 64
#define BS_ (B_*S_)   // 4096

// ---------------- scratch ----------------
__device__ float g_Qh[B_*H_*S_*DK_];   // [B,H,S,DK] (tf32-rounded)
__device__ float g_Kh[B_*H_*S_*DK_];
__device__ float g_Vh[B_*H_*S_*DK_];
__device__ float g_ctx[BS_*D_];        // concat [B,S,D] (tf32-rounded)
__device__ float g_x[BS_*D_];          // pre-LN (full fp32)
__device__ float g_rW[4][D_*D_];       // tf32-rounded weights (q,k,v,o)
__device__ float g_rX[3][BS_*D_];      // tf32-rounded inputs (q,k,v)
__device__ int   g_mflag[B_*16*32];    // per (b, qtile128, ktile64): any mask zero?

// ---------------- helpers ----------------
__device__ __forceinline__ float tf32r(float x) {
    unsigned u;
    asm("cvt.rna.tf32.f32 %0, %1;" : "=r"(u) : "f"(x));
    return __uint_as_float(u);
}

__device__ __forceinline__ void mma8(float& c0, float& c1, float& c2, float& c3,
                                     unsigned a0, unsigned a1, unsigned a2, unsigned a3,
                                     unsigned b0, unsigned b1) {
    asm volatile(
        "mma.sync.aligned.m16n8k8.row.col.f32.tf32.tf32.f32 "
        "{%0,%1,%2,%3},{%4,%5,%6,%7},{%8,%9},{%0,%1,%2,%3};"
        : "+f"(c0), "+f"(c1), "+f"(c2), "+f"(c3)
        : "r"(a0), "r"(a1), "r"(a2), "r"(a3), "r"(b0), "r"(b1));
}

__device__ __forceinline__ void cpasync16(unsigned dst, const void* src) {
    asm volatile("cp.async.cg.shared.global [%0], [%1], 16;" :: "r"(dst), "l"(src));
}
#define CP_COMMIT() asm volatile("cp.async.commit_group;")
#define CP_WAIT1()  asm volatile("cp.async.wait_group 1;")
#define CP_WAIT0()  asm volatile("cp.async.wait_group 0;")

// ===========================================================================
// Prep (single launch): tf32-round 3 inputs + 4 weights.  grid.y selects src.
// ===========================================================================
__global__ void prep_all(const float* __restrict__ q, const float* __restrict__ k,
                         const float* __restrict__ v, const float* __restrict__ Wq,
                         const float* __restrict__ Wk, const float* __restrict__ Wv,
                         const float* __restrict__ Wo)
{
    const int which = blockIdx.y;
    const float* src;
    float* dst;
    int n4;
    if (which < 3) {
        src = (which == 0) ? q : (which == 1) ? k : v;
        dst = g_rX[which];
        n4  = BS_ * D_ / 4;
    } else {
        src = (which == 3) ? Wq : (which == 4) ? Wk : (which == 5) ? Wv : Wo;
        dst = g_rW[which - 3];
        n4  = D_ * D_ / 4;
    }
    int i = blockIdx.x * 256 + threadIdx.x;
    if (i < n4) {
        float4 a = *(const float4*)(src + (size_t)i * 4);
        float4 o;
        o.x = tf32r(a.x); o.y = tf32r(a.y); o.z = tf32r(a.z); o.w = tf32r(a.w);
        *(float4*)(dst + (size_t)i * 4) = o;
    }
}

// ===========================================================================
// Mask summary: flag per (b, qtile 128, ktile 64) whether any zero present
// ===========================================================================
__global__ void maskflag_kernel(const int* __restrict__ mask)
{
    const int kt = blockIdx.x, qt = blockIdx.y, b = blockIdx.z;
    const int* mb = mask + ((size_t)b * S_ + qt * 128) * S_ + kt * 64;
    const int t = threadIdx.x;
    int anyz = 0;
#pragma unroll
    for (int i = 0; i < 8; i++) {
        int lin = t + 256 * i;
        int row = lin >> 4;
        int c4  = (lin & 15) * 4;
        int4 v = *(const int4*)(mb + (size_t)row * S_ + c4);
        anyz |= (v.x == 0) | (v.y == 0) | (v.z == 0) | (v.w == 0);
    }
    anyz = __syncthreads_or(anyz);
    if (t == 0) g_mflag[(b * 16 + qt) * 32 + kt] = anyz;
}

// ===========================================================================
// tf32 GEMM, cp.async 2-stage, BM=BN=128, BK=32, 8 warps (64x32 each).
// mode 0: grid.z selects q/k/v; scatter tf32r(C+bias) to head layout
// mode 1: g_x = C(ctx @ Wo^T) + bias + res (fp32)
// ===========================================================================
#define GAST 36
#define GEMM_STAGE_FLOATS (128*GAST*2)     // 9216
#define GEMM_SMEM (2*GEMM_STAGE_FLOATS*4)  // 73728 bytes

__global__ __launch_bounds__(256) void gemm_tc(const float* __restrict__ bias0,
                                               const float* __restrict__ bias1,
                                               const float* __restrict__ bias2,
                                               const float* __restrict__ res,
                                               int mode)
{
    extern __shared__ float gsm[];

    const int which = (mode == 1) ? 0 : blockIdx.z;
    const float* bias = (which == 0) ? bias0 : (which == 1) ? bias1 : bias2;
    const float* X = (mode == 1) ? (const float*)g_ctx : (const float*)g_rX[which];
    const float* W = (mode == 1) ? (const float*)g_rW[3] : (const float*)g_rW[which];
    float* outp = (which == 0) ? g_Qh : (which == 1) ? g_Kh : g_Vh;

    const int bm = blockIdx.y * 128;
    const int bn = blockIdx.x * 128;
    const int t    = threadIdx.x;
    const int w    = t >> 5;
    const int lane = t & 31;
    const int gid  = lane >> 2;
    const int tid  = lane & 3;
    const int wm   = (w & 1) * 64;
    const int wn   = (w >> 1) * 32;

    const unsigned smaddr = (unsigned)__cvta_generic_to_shared(gsm);

    float c[4][4][4];
#pragma unroll
    for (int i = 0; i < 4; i++)
#pragma unroll
        for (int j = 0; j < 4; j++)
#pragma unroll
            for (int r = 0; r < 4; r++) c[i][j][r] = 0.f;

    {
        unsigned ab = smaddr;
        unsigned bb = ab + 128 * GAST * 4;
#pragma unroll
        for (int i = 0; i < 4; i++) {
            int idx = t + 256 * i;
            int row = idx >> 3;
            int c4  = (idx & 7) << 2;
            cpasync16(ab + (row * GAST + c4) * 4, X + (size_t)(bm + row) * D_ + c4);
            cpasync16(bb + (row * GAST + c4) * 4, W + (size_t)(bn + row) * D_ + c4);
        }
        CP_COMMIT();
    }

    for (int it = 0; it < D_ / 32; it++) {
        const int cur = it & 1;
        if (it + 1 < D_ / 32) {
            const int k0 = (it + 1) * 32;
            unsigned ab = smaddr + (cur ^ 1) * GEMM_STAGE_FLOATS * 4;
            unsigned bb = ab + 128 * GAST * 4;
#pragma unroll
            for (int i = 0; i < 4; i++) {
                int idx = t + 256 * i;
                int row = idx >> 3;
                int c4  = (idx & 7) << 2;
                cpasync16(ab + (row * GAST + c4) * 4, X + (size_t)(bm + row) * D_ + k0 + c4);
                cpasync16(bb + (row * GAST + c4) * 4, W + (size_t)(bn + row) * D_ + k0 + c4);
            }
            CP_COMMIT();
            CP_WAIT1();
        } else {
            CP_WAIT0();
        }
        __syncthreads();

        const float* Ab = gsm + cur * GEMM_STAGE_FLOATS;
        const float* Bb = Ab + 128 * GAST;

#pragma unroll
        for (int ks = 0; ks < 4; ks++) {
            const int k = ks * 8;
            unsigned a0[4], a1[4], a2[4], a3[4], bf0[4], bf1[4];
#pragma unroll
            for (int i = 0; i < 4; i++) {
                int r0 = wm + i * 16 + gid;
                a0[i] = __float_as_uint(Ab[(r0    ) * GAST + k + tid]);
                a1[i] = __float_as_uint(Ab[(r0 + 8) * GAST + k + tid]);
                a2[i] = __float_as_uint(Ab[(r0    ) * GAST + k + tid + 4]);
                a3[i] = __float_as_uint(Ab[(r0 + 8) * GAST + k + tid + 4]);
            }
#pragma unroll
            for (int j = 0; j < 4; j++) {
                int n0 = wn + j * 8 + gid;
                bf0[j] = __float_as_uint(Bb[n0 * GAST + k + tid]);
                bf1[j] = __float_as_uint(Bb[n0 * GAST + k + tid + 4]);
            }
#pragma unroll
            for (int i = 0; i < 4; i++)
#pragma unroll
                for (int j = 0; j < 4; j++)
                    mma8(c[i][j][0], c[i][j][1], c[i][j][2], c[i][j][3],
                         a0[i], a1[i], a2[i], a3[i], bf0[j], bf1[j]);
        }
        __syncthreads();
    }

#pragma unroll
    for (int i = 0; i < 4; i++) {
        int r0 = bm + wm + i * 16 + gid;
        int r1 = r0 + 8;
#pragma unroll
        for (int j = 0; j < 4; j++) {
            int n0 = bn + wn + j * 8 + tid * 2;
            int n1 = n0 + 1;
            if (mode == 0) {
                int b0i = r0 >> 11, s0 = r0 & (S_ - 1);
                int b1i = r1 >> 11, s1 = r1 & (S_ - 1);
                int h0 = n0 >> 6, d0 = n0 & 63;
                int h1 = n1 >> 6, d1 = n1 & 63;
                outp[(((size_t)(b0i * H_ + h0)) * S_ + s0) * DK_ + d0] = tf32r(c[i][j][0] + bias[n0]);
                outp[(((size_t)(b0i * H_ + h1)) * S_ + s0) * DK_ + d1] = tf32r(c[i][j][1] + bias[n1]);
                outp[(((size_t)(b1i * H_ + h0)) * S_ + s1) * DK_ + d0] = tf32r(c[i][j][2] + bias[n0]);
                outp[(((size_t)(b1i * H_ + h1)) * S_ + s1) * DK_ + d1] = tf32r(c[i][j][3] + bias[n1]);
            } else {
                g_x[(size_t)r0 * D_ + n0] = c[i][j][0] + bias[n0] + res[(size_t)r0 * D_ + n0];
                g_x[(size_t)r0 * D_ + n1] = c[i][j][1] + bias[n1] + res[(size_t)r0 * D_ + n1];
                g_x[(size_t)r1 * D_ + n0] = c[i][j][2] + bias[n0] + res[(size_t)r1 * D_ + n0];
                g_x[(size_t)r1 * D_ + n1] = c[i][j][3] + bias[n1] + res[(size_t)r1 * D_ + n1];
            }
        }
    }
}

// ===========================================================================
// Flash attention, tf32 mma, cp.async double-buffered K/V.
// Bq=128 (8 warps x 16 rows), Bk=64.
// smem: Qs[128][68], Ks[2][64][68], Vs[2][64][72], Ps[128][68]
// ===========================================================================
#define QST 68
#define VST 72
#define F_QS   0
#define F_KS   (128*QST)                 // + st*64*QST
#define F_VS   (F_KS + 2*64*QST)         // + st*64*VST
#define F_PS   (F_VS + 2*64*VST)
#define FLASH_FLOATS (F_PS + 128*QST)    // 35328
#define FLASH_SMEM   (FLASH_FLOATS*4)    // 141312 B

__global__ __launch_bounds__(256) void flash_tc(const int* __restrict__ mask)
{
    extern __shared__ float sm[];
    float* Qs = sm + F_QS;
    float* Ps = sm + F_PS;

    const int b  = blockIdx.z;
    const int h  = blockIdx.y;
    const int q0 = blockIdx.x * 128;
    const int t    = threadIdx.x;
    const int w    = t >> 5;
    const int lane = t & 31;
    const int gid  = lane >> 2;
    const int tid  = lane & 3;

    const float* Qg = g_Qh + ((size_t)(b * H_ + h)) * S_ * DK_;
    const float* Kg = g_Kh + ((size_t)(b * H_ + h)) * S_ * DK_;
    const float* Vg = g_Vh + ((size_t)(b * H_ + h)) * S_ * DK_;
    const int* mbase = mask + (size_t)b * S_ * S_;
    const int* mflag = g_mflag + (b * 16 + blockIdx.x) * 32;

    const unsigned smaddr = (unsigned)__cvta_generic_to_shared(sm);

    // Q tile: plain loads (consumed after first barrier)
#pragma unroll
    for (int i = 0; i < 8; i++) {
        int l4  = t + 256 * i;
        int row = l4 >> 4;
        int dg  = (l4 & 15) << 2;
        *(float4*)(Qs + row * QST + dg) = *(const float4*)(Qg + (size_t)(q0 + row) * DK_ + dg);
    }

    // prefetch K/V tile 0 into stage 0
    {
        unsigned ka = smaddr + (F_KS + 0 * 64 * QST) * 4;
        unsigned va = smaddr + (F_VS + 0 * 64 * VST) * 4;
#pragma unroll
        for (int i = 0; i < 4; i++) {
            int l4  = t + 256 * i;
            int row = l4 >> 4;
            int dg  = (l4 & 15) << 2;
            cpasync16(ka + (row * QST + dg) * 4, Kg + (size_t)row * DK_ + dg);
            cpasync16(va + (row * VST + dg) * 4, Vg + (size_t)row * DK_ + dg);
        }
        CP_COMMIT();
    }

    float o[8][4];
#pragma unroll
    for (int j = 0; j < 8; j++)
#pragma unroll
        for (int r = 0; r < 4; r++) o[j][r] = 0.f;
    float mprev0 = -1e30f, mprev1 = -1e30f, lsum0 = 0.f, lsum1 = 0.f;

    const int rloc0 = w * 16 + gid;
    const int rloc1 = rloc0 + 8;

    for (int kt = 0; kt < S_ / 64; kt++) {
        const int cur = kt & 1;
        __syncthreads();   // all warps done reading stage cur^1 (tile kt-1)

        if (kt + 1 < S_ / 64) {
            const int k0n = (kt + 1) * 64;
            unsigned ka = smaddr + (F_KS + (cur ^ 1) * 64 * QST) * 4;
            unsigned va = smaddr + (F_VS + (cur ^ 1) * 64 * VST) * 4;
#pragma unroll
            for (int i = 0; i < 4; i++) {
                int l4  = t + 256 * i;
                int row = l4 >> 4;
                int dg  = (l4 & 15) << 2;
                cpasync16(ka + (row * QST + dg) * 4, Kg + (size_t)(k0n + row) * DK_ + dg);
                cpasync16(va + (row * VST + dg) * 4, Vg + (size_t)(k0n + row) * DK_ + dg);
            }
            CP_COMMIT();
            CP_WAIT1();
        } else {
            CP_WAIT0();
        }
        __syncthreads();   // stage cur data visible to all

        const float* Ks = sm + F_KS + cur * 64 * QST;
        const float* Vs = sm + F_VS + cur * 64 * VST;
        const int k0 = kt * 64;

        // ---- S = Q @ K^T ----
        float s[8][4];
#pragma unroll
        for (int j = 0; j < 8; j++)
#pragma unroll
            for (int r = 0; r < 4; r++) s[j][r] = 0.f;

#pragma unroll
        for (int kk = 0; kk < 8; kk++) {
            const int k = kk * 8;
            unsigned qa0 = __float_as_uint(Qs[rloc0 * QST + k + tid]);
            unsigned qa1 = __float_as_uint(Qs[rloc1 * QST + k + tid]);
            unsigned qa2 = __float_as_uint(Qs[rloc0 * QST + k + tid + 4]);
            unsigned qa3 = __float_as_uint(Qs[rloc1 * QST + k + tid + 4]);
#pragma unroll
            for (int j = 0; j < 8; j++) {
                unsigned b0 = __float_as_uint(Ks[(j * 8 + gid) * QST + k + tid]);
                unsigned b1 = __float_as_uint(Ks[(j * 8 + gid) * QST + k + tid + 4]);
                mma8(s[j][0], s[j][1], s[j][2], s[j][3], qa0, qa1, qa2, qa3, b0, b1);
            }
        }

        // ---- scale (+mask only if tile has zeros) ----
        const float scale = 0.125f;
#pragma unroll
        for (int j = 0; j < 8; j++) {
            s[j][0] *= scale; s[j][1] *= scale;
            s[j][2] *= scale; s[j][3] *= scale;
        }
        if (mflag[kt]) {
            const int gr0 = q0 + rloc0;
            const int gr1 = q0 + rloc1;
#pragma unroll
            for (int j = 0; j < 8; j++) {
                int col = k0 + j * 8 + tid * 2;
                const int* m0p = mbase + (size_t)gr0 * S_ + col;
                const int* m1p = mbase + (size_t)gr1 * S_ + col;
                if (m0p[0] == 0) s[j][0] = -1e9f;
                if (m0p[1] == 0) s[j][1] = -1e9f;
                if (m1p[0] == 0) s[j][2] = -1e9f;
                if (m1p[1] == 0) s[j][3] = -1e9f;
            }
        }

        // ---- online softmax ----
        float mx0 = -1e30f, mx1 = -1e30f;
#pragma unroll
        for (int j = 0; j < 8; j++) {
            mx0 = fmaxf(mx0, fmaxf(s[j][0], s[j][1]));
            mx1 = fmaxf(mx1, fmaxf(s[j][2], s[j][3]));
        }
#pragma unroll
        for (int off = 1; off <= 2; off <<= 1) {
            mx0 = fmaxf(mx0, __shfl_xor_sync(0xffffffffu, mx0, off));
            mx1 = fmaxf(mx1, __shfl_xor_sync(0xffffffffu, mx1, off));
        }
        float mn0 = fmaxf(mprev0, mx0);
        float mn1 = fmaxf(mprev1, mx1);
        float f0 = __expf(mprev0 - mn0);
        float f1 = __expf(mprev1 - mn1);
        float rs0 = 0.f, rs1 = 0.f;
#pragma unroll
        for (int j = 0; j < 8; j++) {
            s[j][0] = __expf(s[j][0] - mn0);
            s[j][1] = __expf(s[j][1] - mn0);
            s[j][2] = __expf(s[j][2] - mn1);
            s[j][3] = __expf(s[j][3] - mn1);
            rs0 += s[j][0] + s[j][1];
            rs1 += s[j][2] + s[j][3];
            int pc = j * 8 + tid * 2;
            *(float2*)(Ps + rloc0 * QST + pc) = make_float2(tf32r(s[j][0]), tf32r(s[j][1]));
            *(float2*)(Ps + rloc1 * QST + pc) = make_float2(tf32r(s[j][2]), tf32r(s[j][3]));
        }
#pragma unroll
        for (int off = 1; off <= 2; off <<= 1) {
            rs0 += __shfl_xor_sync(0xffffffffu, rs0, off);
            rs1 += __shfl_xor_sync(0xffffffffu, rs1, off);
        }
        lsum0 = lsum0 * f0 + rs0;
        lsum1 = lsum1 * f1 + rs1;
        mprev0 = mn0;
        mprev1 = mn1;
#pragma unroll
        for (int j = 0; j < 8; j++) {
            o[j][0] *= f0; o[j][1] *= f0;
            o[j][2] *= f1; o[j][3] *= f1;
        }
        __syncwarp();   // P rows are warp-private: warp-level sync suffices

        // ---- O += P @ V ----
#pragma unroll
        for (int kk = 0; kk < 8; kk++) {
            const int k = kk * 8;
            unsigned pa0 = __float_as_uint(Ps[rloc0 * QST + k + tid]);
            unsigned pa1 = __float_as_uint(Ps[rloc1 * QST + k + tid]);
            unsigned pa2 = __float_as_uint(Ps[rloc0 * QST + k + tid + 4]);
            unsigned pa3 = __float_as_uint(Ps[rloc1 * QST + k + tid + 4]);
#pragma unroll
            for (int j = 0; j < 8; j++) {
                unsigned b0 = __float_as_uint(Vs[(k + tid)     * VST + j * 8 + gid]);
                unsigned b1 = __float_as_uint(Vs[(k + tid + 4) * VST + j * 8 + gid]);
                mma8(o[j][0], o[j][1], o[j][2], o[j][3], pa0, pa1, pa2, pa3, b0, b1);
            }
        }
    }

    // epilogue -> g_ctx (tf32-rounded; feeds the out-proj mma)
    float inv0 = 1.0f / lsum0;
    float inv1 = 1.0f / lsum1;
    float* out0 = g_ctx + ((size_t)b * S_ + (q0 + rloc0)) * D_ + h * DK_;
    float* out1 = g_ctx + ((size_t)b * S_ + (q0 + rloc1)) * D_ + h * DK_;
#pragma unroll
    for (int j = 0; j < 8; j++) {
        int col = j * 8 + tid * 2;
        out0[col + 0] = tf32r(o[j][0] * inv0);
        out0[col + 1] = tf32r(o[j][1] * inv0);
        out1[col + 0] = tf32r(o[j][2] * inv1);
        out1[col + 1] = tf32r(o[j][3] * inv1);
    }
}

// ===========================================================================
// LayerNorm over D=1024 per row
// ===========================================================================
__global__ __launch_bounds__(256) void ln_kernel(const float* __restrict__ gamma,
                                                 const float* __restrict__ beta,
                                                 float* __restrict__ out)
{
    const int row = blockIdx.x;
    const int t   = threadIdx.x;
    const float* x = g_x + (size_t)row * D_;

    float4 v = *(const float4*)(x + t * 4);
    float s  = v.x + v.y + v.z + v.w;
    float ss = v.x * v.x + v.y * v.y + v.z * v.z + v.w * v.w;
#pragma unroll
    for (int off = 16; off >= 1; off >>= 1) {
        s  += __shfl_xor_sync(0xffffffffu, s,  off);
        ss += __shfl_xor_sync(0xffffffffu, ss, off);
    }
    __shared__ float red[8][2];
    int w = t >> 5, ln = t & 31;
    if (ln == 0) { red[w][0] = s; red[w][1] = ss; }
    __syncthreads();
    s = 0.f; ss = 0.f;
#pragma unroll
    for (int i = 0; i < 8; i++) { s += red[i][0]; ss += red[i][1]; }

    float mean = s * (1.0f / D_);
    float var  = ss * (1.0f / D_) - mean * mean;
    float rstd = rsqrtf(var + 1e-5f);

    float4 g  = *(const float4*)(gamma + t * 4);
    float4 be = *(const float4*)(beta + t * 4);
    float4 ov;
    ov.x = (v.x - mean) * rstd * g.x + be.x;
    ov.y = (v.y - mean) * rstd * g.y + be.y;
    ov.z = (v.z - mean) * rstd * g.z + be.z;
    ov.w = (v.w - mean) * rstd * g.w + be.w;
    *(float4*)(out + (size_t)row * D_ + t * 4) = ov;
}

// ===========================================================================
extern "C" void kernel_launch(void* const* d_in, const int* in_sizes, int n_in,
                              void* d_out, int out_size)
{
    const float* q     = (const float*)d_in[0];
    const float* k     = (const float*)d_in[1];
    const float* v     = (const float*)d_in[2];
    const int*   mask  = (const int*)  d_in[3];
    const float* Wq    = (const float*)d_in[4];
    const float* bq    = (const float*)d_in[5];
    const float* Wk    = (const float*)d_in[6];
    const float* bk    = (const float*)d_in[7];
    const float* Wv    = (const float*)d_in[8];
    const float* bv    = (const float*)d_in[9];
    const float* Wo    = (const float*)d_in[10];
    const float* bo    = (const float*)d_in[11];
    const float* gamma = (const float*)d_in[12];
    const float* beta  = (const float*)d_in[13];
    float* out = (float*)d_out;

    // single prep launch: grid.y selects which tensor; guard handles sizes
    const int nX4 = BS_ * D_ / 4;   // 1048576 -> 4096 blocks of 256
    prep_all<<<dim3(nX4 / 256, 7), 256>>>(q, k, v, Wq, Wk, Wv, Wo);

    maskflag_kernel<<<dim3(32, 16, B_), 256>>>(mask);

    cudaFuncSetAttribute(gemm_tc, cudaFuncAttributeMaxDynamicSharedMemorySize, GEMM_SMEM);
    // QKV projections in ONE launch (grid.z = 3)
    gemm_tc<<<dim3(D_ / 128, BS_ / 128, 3), 256, GEMM_SMEM>>>(bq, bk, bv, nullptr, 0);

    cudaFuncSetAttribute(flash_tc, cudaFuncAttributeMaxDynamicSharedMemorySize, FLASH_SMEM);
    flash_tc<<<dim3(S_ / 128, H_, B_), 256, FLASH_SMEM>>>(mask);

    gemm_tc<<<dim3(D_ / 128, BS_ / 128, 1), 256, GEMM_SMEM>>>(bo, nullptr, nullptr, q, 1);

    ln_kernel<<<BS_, 256>>>(gamma, beta, out);
}

// round 14
// speedup vs baseline: 3.7508x; 1.0753x over previous
#include <cuda_runtime.h>
#include <math.h>

#define B_  2
#define S_  2048
#define D_  1024
#define H_  16
#define DK_ 64
#define BS_ (B_*S_)   // 4096

// ---------------- scratch ----------------
__device__ float g_Qh[B_*H_*S_*DK_];   // [B,H,S,DK] (tf32-rounded)
__device__ float g_Kh[B_*H_*S_*DK_];
__device__ float g_Vh[B_*H_*S_*DK_];
__device__ float g_ctx[BS_*D_];        // concat [B,S,D] (tf32-rounded)
__device__ float g_x[BS_*D_];          // pre-LN (full fp32)
__device__ float g_rW[4][D_*D_];       // tf32-rounded weights (q,k,v,o)
__device__ float g_rX[3][BS_*D_];      // tf32-rounded inputs (q,k,v)
__device__ int   g_mflag[B_*16*32];    // per (b, qtile128, ktile64): any mask zero?

// ---------------- helpers ----------------
__device__ __forceinline__ float tf32r(float x) {
    unsigned u;
    asm("cvt.rna.tf32.f32 %0, %1;" : "=r"(u) : "f"(x));
    return __uint_as_float(u);
}

__device__ __forceinline__ void mma8(float& c0, float& c1, float& c2, float& c3,
                                     unsigned a0, unsigned a1, unsigned a2, unsigned a3,
                                     unsigned b0, unsigned b1) {
    asm volatile(
        "mma.sync.aligned.m16n8k8.row.col.f32.tf32.tf32.f32 "
        "{%0,%1,%2,%3},{%4,%5,%6,%7},{%8,%9},{%0,%1,%2,%3};"
        : "+f"(c0), "+f"(c1), "+f"(c2), "+f"(c3)
        : "r"(a0), "r"(a1), "r"(a2), "r"(a3), "r"(b0), "r"(b1));
}

__device__ __forceinline__ void cpasync16(unsigned dst, const void* src) {
    asm volatile("cp.async.cg.shared.global [%0], [%1], 16;" :: "r"(dst), "l"(src));
}
#define CP_COMMIT() asm volatile("cp.async.commit_group;")
#define CP_WAIT1()  asm volatile("cp.async.wait_group 1;")
#define CP_WAIT0()  asm volatile("cp.async.wait_group 0;")

// ===========================================================================
// Prep (single launch): tf32-round 3 inputs + 4 weights.  grid.y selects src.
// ===========================================================================
__global__ void prep_all(const float* __restrict__ q, const float* __restrict__ k,
                         const float* __restrict__ v, const float* __restrict__ Wq,
                         const float* __restrict__ Wk, const float* __restrict__ Wv,
                         const float* __restrict__ Wo)
{
    const int which = blockIdx.y;
    const float* src;
    float* dst;
    int n4;
    if (which < 3) {
        src = (which == 0) ? q : (which == 1) ? k : v;
        dst = g_rX[which];
        n4  = BS_ * D_ / 4;
    } else {
        src = (which == 3) ? Wq : (which == 4) ? Wk : (which == 5) ? Wv : Wo;
        dst = g_rW[which - 3];
        n4  = D_ * D_ / 4;
    }
    int i = blockIdx.x * 256 + threadIdx.x;
    if (i < n4) {
        float4 a = *(const float4*)(src + (size_t)i * 4);
        float4 o;
        o.x = tf32r(a.x); o.y = tf32r(a.y); o.z = tf32r(a.z); o.w = tf32r(a.w);
        *(float4*)(dst + (size_t)i * 4) = o;
    }
}

// ===========================================================================
// Mask summary: flag per (b, qtile 128, ktile 64) whether any zero present
// ===========================================================================
__global__ void maskflag_kernel(const int* __restrict__ mask)
{
    const int kt = blockIdx.x, qt = blockIdx.y, b = blockIdx.z;
    const int* mb = mask + ((size_t)b * S_ + qt * 128) * S_ + kt * 64;
    const int t = threadIdx.x;
    int anyz = 0;
#pragma unroll
    for (int i = 0; i < 8; i++) {
        int lin = t + 256 * i;
        int row = lin >> 4;
        int c4  = (lin & 15) * 4;
        int4 v = *(const int4*)(mb + (size_t)row * S_ + c4);
        anyz |= (v.x == 0) | (v.y == 0) | (v.z == 0) | (v.w == 0);
    }
    anyz = __syncthreads_or(anyz);
    if (t == 0) g_mflag[(b * 16 + qt) * 32 + kt] = anyz;
}

// ===========================================================================
// tf32 GEMM, cp.async 2-stage, BM=BN=128, BK=32, 8 warps (64x32 each).
// mode 0: grid.z selects q/k/v; scatter tf32r(C+bias) to head layout
// mode 1: g_x = C(ctx @ Wo^T) + bias + res (fp32)
// ===========================================================================
#define GAST 36
#define GEMM_STAGE_FLOATS (128*GAST*2)     // 9216
#define GEMM_SMEM (2*GEMM_STAGE_FLOATS*4)  // 73728 bytes

__global__ __launch_bounds__(256) void gemm_tc(const float* __restrict__ bias0,
                                               const float* __restrict__ bias1,
                                               const float* __restrict__ bias2,
                                               const float* __restrict__ res,
                                               int mode)
{
    extern __shared__ float gsm[];

    const int which = (mode == 1) ? 0 : blockIdx.z;
    const float* bias = (which == 0) ? bias0 : (which == 1) ? bias1 : bias2;
    const float* X = (mode == 1) ? (const float*)g_ctx : (const float*)g_rX[which];
    const float* W = (mode == 1) ? (const float*)g_rW[3] : (const float*)g_rW[which];
    float* outp = (which == 0) ? g_Qh : (which == 1) ? g_Kh : g_Vh;

    const int bm = blockIdx.y * 128;
    const int bn = blockIdx.x * 128;
    const int t    = threadIdx.x;
    const int w    = t >> 5;
    const int lane = t & 31;
    const int gid  = lane >> 2;
    const int tid  = lane & 3;
    const int wm   = (w & 1) * 64;
    const int wn   = (w >> 1) * 32;

    const unsigned smaddr = (unsigned)__cvta_generic_to_shared(gsm);

    float c[4][4][4];
#pragma unroll
    for (int i = 0; i < 4; i++)
#pragma unroll
        for (int j = 0; j < 4; j++)
#pragma unroll
            for (int r = 0; r < 4; r++) c[i][j][r] = 0.f;

    {
        unsigned ab = smaddr;
        unsigned bb = ab + 128 * GAST * 4;
#pragma unroll
        for (int i = 0; i < 4; i++) {
            int idx = t + 256 * i;
            int row = idx >> 3;
            int c4  = (idx & 7) << 2;
            cpasync16(ab + (row * GAST + c4) * 4, X + (size_t)(bm + row) * D_ + c4);
            cpasync16(bb + (row * GAST + c4) * 4, W + (size_t)(bn + row) * D_ + c4);
        }
        CP_COMMIT();
    }

    for (int it = 0; it < D_ / 32; it++) {
        const int cur = it & 1;
        if (it + 1 < D_ / 32) {
            const int k0 = (it + 1) * 32;
            unsigned ab = smaddr + (cur ^ 1) * GEMM_STAGE_FLOATS * 4;
            unsigned bb = ab + 128 * GAST * 4;
#pragma unroll
            for (int i = 0; i < 4; i++) {
                int idx = t + 256 * i;
                int row = idx >> 3;
                int c4  = (idx & 7) << 2;
                cpasync16(ab + (row * GAST + c4) * 4, X + (size_t)(bm + row) * D_ + k0 + c4);
                cpasync16(bb + (row * GAST + c4) * 4, W + (size_t)(bn + row) * D_ + k0 + c4);
            }
            CP_COMMIT();
            CP_WAIT1();
        } else {
            CP_WAIT0();
        }
        __syncthreads();

        const float* Ab = gsm + cur * GEMM_STAGE_FLOATS;
        const float* Bb = Ab + 128 * GAST;

#pragma unroll
        for (int ks = 0; ks < 4; ks++) {
            const int k = ks * 8;
            unsigned a0[4], a1[4], a2[4], a3[4], bf0[4], bf1[4];
#pragma unroll
            for (int i = 0; i < 4; i++) {
                int r0 = wm + i * 16 + gid;
                a0[i] = __float_as_uint(Ab[(r0    ) * GAST + k + tid]);
                a1[i] = __float_as_uint(Ab[(r0 + 8) * GAST + k + tid]);
                a2[i] = __float_as_uint(Ab[(r0    ) * GAST + k + tid + 4]);
                a3[i] = __float_as_uint(Ab[(r0 + 8) * GAST + k + tid + 4]);
            }
#pragma unroll
            for (int j = 0; j < 4; j++) {
                int n0 = wn + j * 8 + gid;
                bf0[j] = __float_as_uint(Bb[n0 * GAST + k + tid]);
                bf1[j] = __float_as_uint(Bb[n0 * GAST + k + tid + 4]);
            }
#pragma unroll
            for (int i = 0; i < 4; i++)
#pragma unroll
                for (int j = 0; j < 4; j++)
                    mma8(c[i][j][0], c[i][j][1], c[i][j][2], c[i][j][3],
                         a0[i], a1[i], a2[i], a3[i], bf0[j], bf1[j]);
        }
        __syncthreads();
    }

#pragma unroll
    for (int i = 0; i < 4; i++) {
        int r0 = bm + wm + i * 16 + gid;
        int r1 = r0 + 8;
#pragma unroll
        for (int j = 0; j < 4; j++) {
            int n0 = bn + wn + j * 8 + tid * 2;
            int n1 = n0 + 1;
            if (mode == 0) {
                int b0i = r0 >> 11, s0 = r0 & (S_ - 1);
                int b1i = r1 >> 11, s1 = r1 & (S_ - 1);
                int h0 = n0 >> 6, d0 = n0 & 63;
                int h1 = n1 >> 6, d1 = n1 & 63;
                outp[(((size_t)(b0i * H_ + h0)) * S_ + s0) * DK_ + d0] = tf32r(c[i][j][0] + bias[n0]);
                outp[(((size_t)(b0i * H_ + h1)) * S_ + s0) * DK_ + d1] = tf32r(c[i][j][1] + bias[n1]);
                outp[(((size_t)(b1i * H_ + h0)) * S_ + s1) * DK_ + d0] = tf32r(c[i][j][2] + bias[n0]);
                outp[(((size_t)(b1i * H_ + h1)) * S_ + s1) * DK_ + d1] = tf32r(c[i][j][3] + bias[n1]);
            } else {
                g_x[(size_t)r0 * D_ + n0] = c[i][j][0] + bias[n0] + res[(size_t)r0 * D_ + n0];
                g_x[(size_t)r0 * D_ + n1] = c[i][j][1] + bias[n1] + res[(size_t)r0 * D_ + n1];
                g_x[(size_t)r1 * D_ + n0] = c[i][j][2] + bias[n0] + res[(size_t)r1 * D_ + n0];
                g_x[(size_t)r1 * D_ + n1] = c[i][j][3] + bias[n1] + res[(size_t)r1 * D_ + n1];
            }
        }
    }
}

// ===========================================================================
// Flash attention, tf32 mma, cp.async double-buffered K/V, Q in REGISTERS.
// Bq=128 (8 warps x 16 rows), Bk=64.
// smem: Ps[128][68] (first holds Q during init), Ks[2][64][68], Vs[2][64][72]
//       = 26624 floats = 104 KB -> 2 blocks/SM
// ===========================================================================
#define QST 68
#define VST 72
#define F_PS   0
#define F_KS   (128*QST)
#define F_VS   (F_KS + 2*64*QST)
#define FLASH_FLOATS (F_VS + 2*64*VST)   // 26624
#define FLASH_SMEM   (FLASH_FLOATS*4)    // 106496 B

__global__ __launch_bounds__(256, 2) void flash_tc(const int* __restrict__ mask)
{
    extern __shared__ float sm[];
    float* Ps = sm + F_PS;   // during init this region holds the Q tile

    const int b  = blockIdx.z;
    const int h  = blockIdx.y;
    const int q0 = blockIdx.x * 128;
    const int t    = threadIdx.x;
    const int w    = t >> 5;
    const int lane = t & 31;
    const int gid  = lane >> 2;
    const int tid  = lane & 3;

    const float* Qg = g_Qh + ((size_t)(b * H_ + h)) * S_ * DK_;
    const float* Kg = g_Kh + ((size_t)(b * H_ + h)) * S_ * DK_;
    const float* Vg = g_Vh + ((size_t)(b * H_ + h)) * S_ * DK_;
    const int* mbase = mask + (size_t)b * S_ * S_;
    const int* mflag = g_mflag + (b * 16 + blockIdx.x) * 32;

    const unsigned smaddr = (unsigned)__cvta_generic_to_shared(sm);

    // stage Q tile into (future) Ps region
#pragma unroll
    for (int i = 0; i < 8; i++) {
        int l4  = t + 256 * i;
        int row = l4 >> 4;
        int dg  = (l4 & 15) << 2;
        *(float4*)(Ps + row * QST + dg) = *(const float4*)(Qg + (size_t)(q0 + row) * DK_ + dg);
    }

    // prefetch K/V tile 0 into stage 0
    {
        unsigned ka = smaddr + (F_KS + 0 * 64 * QST) * 4;
        unsigned va = smaddr + (F_VS + 0 * 64 * VST) * 4;
#pragma unroll
        for (int i = 0; i < 4; i++) {
            int l4  = t + 256 * i;
            int row = l4 >> 4;
            int dg  = (l4 & 15) << 2;
            cpasync16(ka + (row * QST + dg) * 4, Kg + (size_t)row * DK_ + dg);
            cpasync16(va + (row * VST + dg) * 4, Vg + (size_t)row * DK_ + dg);
        }
        CP_COMMIT();
    }

    const int rloc0 = w * 16 + gid;
    const int rloc1 = rloc0 + 8;

    __syncthreads();   // Q staging complete

    // Q fragments -> registers (own-stripe reads; reused for all 32 k-tiles)
    unsigned qr[32];
#pragma unroll
    for (int kk = 0; kk < 8; kk++) {
        const int k = kk * 8;
        qr[kk * 4 + 0] = __float_as_uint(Ps[rloc0 * QST + k + tid]);
        qr[kk * 4 + 1] = __float_as_uint(Ps[rloc1 * QST + k + tid]);
        qr[kk * 4 + 2] = __float_as_uint(Ps[rloc0 * QST + k + tid + 4]);
        qr[kk * 4 + 3] = __float_as_uint(Ps[rloc1 * QST + k + tid + 4]);
    }
    // After this point each warp only touches its own 16-row stripe of Ps,
    // so no extra block barrier is needed before P writes.

    float o[8][4];
#pragma unroll
    for (int j = 0; j < 8; j++)
#pragma unroll
        for (int r = 0; r < 4; r++) o[j][r] = 0.f;
    float mprev0 = -1e30f, mprev1 = -1e30f, lsum0 = 0.f, lsum1 = 0.f;

    for (int kt = 0; kt < S_ / 64; kt++) {
        const int cur = kt & 1;
        __syncthreads();   // all warps done with stage cur^1 (tile kt-1)

        if (kt + 1 < S_ / 64) {
            const int k0n = (kt + 1) * 64;
            unsigned ka = smaddr + (F_KS + (cur ^ 1) * 64 * QST) * 4;
            unsigned va = smaddr + (F_VS + (cur ^ 1) * 64 * VST) * 4;
#pragma unroll
            for (int i = 0; i < 4; i++) {
                int l4  = t + 256 * i;
                int row = l4 >> 4;
                int dg  = (l4 & 15) << 2;
                cpasync16(ka + (row * QST + dg) * 4, Kg + (size_t)(k0n + row) * DK_ + dg);
                cpasync16(va + (row * VST + dg) * 4, Vg + (size_t)(k0n + row) * DK_ + dg);
            }
            CP_COMMIT();
            CP_WAIT1();
        } else {
            CP_WAIT0();
        }
        __syncthreads();   // stage cur visible

        const float* Ks = sm + F_KS + cur * 64 * QST;
        const float* Vs = sm + F_VS + cur * 64 * VST;
        const int k0 = kt * 64;

        // ---- S = Q @ K^T (Q from registers) ----
        float s[8][4];
#pragma unroll
        for (int j = 0; j < 8; j++)
#pragma unroll
            for (int r = 0; r < 4; r++) s[j][r] = 0.f;

#pragma unroll
        for (int kk = 0; kk < 8; kk++) {
            const int k = kk * 8;
            const unsigned qa0 = qr[kk * 4 + 0];
            const unsigned qa1 = qr[kk * 4 + 1];
            const unsigned qa2 = qr[kk * 4 + 2];
            const unsigned qa3 = qr[kk * 4 + 3];
#pragma unroll
            for (int j = 0; j < 8; j++) {
                unsigned b0 = __float_as_uint(Ks[(j * 8 + gid) * QST + k + tid]);
                unsigned b1 = __float_as_uint(Ks[(j * 8 + gid) * QST + k + tid + 4]);
                mma8(s[j][0], s[j][1], s[j][2], s[j][3], qa0, qa1, qa2, qa3, b0, b1);
            }
        }

        // ---- scale (+mask only if tile has zeros) ----
        const float scale = 0.125f;
#pragma unroll
        for (int j = 0; j < 8; j++) {
            s[j][0] *= scale; s[j][1] *= scale;
            s[j][2] *= scale; s[j][3] *= scale;
        }
        if (mflag[kt]) {
            const int gr0 = q0 + rloc0;
            const int gr1 = q0 + rloc1;
#pragma unroll
            for (int j = 0; j < 8; j++) {
                int col = k0 + j * 8 + tid * 2;
                const int* m0p = mbase + (size_t)gr0 * S_ + col;
                const int* m1p = mbase + (size_t)gr1 * S_ + col;
                if (m0p[0] == 0) s[j][0] = -1e9f;
                if (m0p[1] == 0) s[j][1] = -1e9f;
                if (m1p[0] == 0) s[j][2] = -1e9f;
                if (m1p[1] == 0) s[j][3] = -1e9f;
            }
        }

        // ---- online softmax ----
        float mx0 = -1e30f, mx1 = -1e30f;
#pragma unroll
        for (int j = 0; j < 8; j++) {
            mx0 = fmaxf(mx0, fmaxf(s[j][0], s[j][1]));
            mx1 = fmaxf(mx1, fmaxf(s[j][2], s[j][3]));
        }
#pragma unroll
        for (int off = 1; off <= 2; off <<= 1) {
            mx0 = fmaxf(mx0, __shfl_xor_sync(0xffffffffu, mx0, off));
            mx1 = fmaxf(mx1, __shfl_xor_sync(0xffffffffu, mx1, off));
        }
        float mn0 = fmaxf(mprev0, mx0);
        float mn1 = fmaxf(mprev1, mx1);
        float f0 = __expf(mprev0 - mn0);
        float f1 = __expf(mprev1 - mn1);
        float rs0 = 0.f, rs1 = 0.f;
#pragma unroll
        for (int j = 0; j < 8; j++) {
            s[j][0] = __expf(s[j][0] - mn0);
            s[j][1] = __expf(s[j][1] - mn0);
            s[j][2] = __expf(s[j][2] - mn1);
            s[j][3] = __expf(s[j][3] - mn1);
            rs0 += s[j][0] + s[j][1];
            rs1 += s[j][2] + s[j][3];
            int pc = j * 8 + tid * 2;
            *(float2*)(Ps + rloc0 * QST + pc) = make_float2(tf32r(s[j][0]), tf32r(s[j][1]));
            *(float2*)(Ps + rloc1 * QST + pc) = make_float2(tf32r(s[j][2]), tf32r(s[j][3]));
        }
#pragma unroll
        for (int off = 1; off <= 2; off <<= 1) {
            rs0 += __shfl_xor_sync(0xffffffffu, rs0, off);
            rs1 += __shfl_xor_sync(0xffffffffu, rs1, off);
        }
        lsum0 = lsum0 * f0 + rs0;
        lsum1 = lsum1 * f1 + rs1;
        mprev0 = mn0;
        mprev1 = mn1;
#pragma unroll
        for (int j = 0; j < 8; j++) {
            o[j][0] *= f0; o[j][1] *= f0;
            o[j][2] *= f1; o[j][3] *= f1;
        }
        __syncwarp();   // P rows are warp-private

        // ---- O += P @ V ----
#pragma unroll
        for (int kk = 0; kk < 8; kk++) {
            const int k = kk * 8;
            unsigned pa0 = __float_as_uint(Ps[rloc0 * QST + k + tid]);
            unsigned pa1 = __float_as_uint(Ps[rloc1 * QST + k + tid]);
            unsigned pa2 = __float_as_uint(Ps[rloc0 * QST + k + tid + 4]);
            unsigned pa3 = __float_as_uint(Ps[rloc1 * QST + k + tid + 4]);
#pragma unroll
            for (int j = 0; j < 8; j++) {
                unsigned b0 = __float_as_uint(Vs[(k + tid)     * VST + j * 8 + gid]);
                unsigned b1 = __float_as_uint(Vs[(k + tid + 4) * VST + j * 8 + gid]);
                mma8(o[j][0], o[j][1], o[j][2], o[j][3], pa0, pa1, pa2, pa3, b0, b1);
            }
        }
    }

    // epilogue -> g_ctx (tf32-rounded; feeds out-proj mma)
    float inv0 = 1.0f / lsum0;
    float inv1 = 1.0f / lsum1;
    float* out0 = g_ctx + ((size_t)b * S_ + (q0 + rloc0)) * D_ + h * DK_;
    float* out1 = g_ctx + ((size_t)b * S_ + (q0 + rloc1)) * D_ + h * DK_;
#pragma unroll
    for (int j = 0; j < 8; j++) {
        int col = j * 8 + tid * 2;
        out0[col + 0] = tf32r(o[j][0] * inv0);
        out0[col + 1] = tf32r(o[j][1] * inv0);
        out1[col + 0] = tf32r(o[j][2] * inv1);
        out1[col + 1] = tf32r(o[j][3] * inv1);
    }
}

// ===========================================================================
// LayerNorm over D=1024 per row
// ===========================================================================
__global__ __launch_bounds__(256) void ln_kernel(const float* __restrict__ gamma,
                                                 const float* __restrict__ beta,
                                                 float* __restrict__ out)
{
    const int row = blockIdx.x;
    const int t   = threadIdx.x;
    const float* x = g_x + (size_t)row * D_;

    float4 v = *(const float4*)(x + t * 4);
    float s  = v.x + v.y + v.z + v.w;
    float ss = v.x * v.x + v.y * v.y + v.z * v.z + v.w * v.w;
#pragma unroll
    for (int off = 16; off >= 1; off >>= 1) {
        s  += __shfl_xor_sync(0xffffffffu, s,  off);
        ss += __shfl_xor_sync(0xffffffffu, ss, off);
    }
    __shared__ float red[8][2];
    int w = t >> 5, ln = t & 31;
    if (ln == 0) { red[w][0] = s; red[w][1] = ss; }
    __syncthreads();
    s = 0.f; ss = 0.f;
#pragma unroll
    for (int i = 0; i < 8; i++) { s += red[i][0]; ss += red[i][1]; }

    float mean = s * (1.0f / D_);
    float var  = ss * (1.0f / D_) - mean * mean;
    float rstd = rsqrtf(var + 1e-5f);

    float4 g  = *(const float4*)(gamma + t * 4);
    float4 be = *(const float4*)(beta + t * 4);
    float4 ov;
    ov.x = (v.x - mean) * rstd * g.x + be.x;
    ov.y = (v.y - mean) * rstd * g.y + be.y;
    ov.z = (v.z - mean) * rstd * g.z + be.z;
    ov.w = (v.w - mean) * rstd * g.w + be.w;
    *(float4*)(out + (size_t)row * D_ + t * 4) = ov;
}

// ===========================================================================
extern "C" void kernel_launch(void* const* d_in, const int* in_sizes, int n_in,
                              void* d_out, int out_size)
{
    const float* q     = (const float*)d_in[0];
    const float* k     = (const float*)d_in[1];
    const float* v     = (const float*)d_in[2];
    const int*   mask  = (const int*)  d_in[3];
    const float* Wq    = (const float*)d_in[4];
    const float* bq    = (const float*)d_in[5];
    const float* Wk    = (const float*)d_in[6];
    const float* bk    = (const float*)d_in[7];
    const float* Wv    = (const float*)d_in[8];
    const float* bv    = (const float*)d_in[9];
    const float* Wo    = (const float*)d_in[10];
    const float* bo    = (const float*)d_in[11];
    const float* gamma = (const float*)d_in[12];
    const float* beta  = (const float*)d_in[13];
    float* out = (float*)d_out;

    const int nX4 = BS_ * D_ / 4;   // 1048576 -> 4096 blocks of 256
    prep_all<<<dim3(nX4 / 256, 7), 256>>>(q, k, v, Wq, Wk, Wv, Wo);

    maskflag_kernel<<<dim3(32, 16, B_), 256>>>(mask);

    cudaFuncSetAttribute(gemm_tc, cudaFuncAttributeMaxDynamicSharedMemorySize, GEMM_SMEM);
    gemm_tc<<<dim3(D_ / 128, BS_ / 128, 3), 256, GEMM_SMEM>>>(bq, bk, bv, nullptr, 0);

    cudaFuncSetAttribute(flash_tc, cudaFuncAttributeMaxDynamicSharedMemorySize, FLASH_SMEM);
    flash_tc<<<dim3(S_ / 128, H_, B_), 256, FLASH_SMEM>>>(mask);

    gemm_tc<<<dim3(D_ / 128, BS_ / 128, 1), 256, GEMM_SMEM>>>(bo, nullptr, nullptr, q, 1);

    ln_kernel<<<BS_, 256>>>(gamma, beta, out);
}

// round 15
// speedup vs baseline: 3.9262x; 1.0468x over previous
#include <cuda_runtime.h>
#include <math.h>

#define B_  2
#define S_  2048
#define D_  1024
#define H_  16
#define DK_ 64
#define BS_ (B_*S_)   // 4096

// ---------------- scratch ----------------
__device__ float g_Qh[B_*H_*S_*DK_];   // [B,H,S,DK]
__device__ float g_Kh[B_*H_*S_*DK_];
__device__ float g_Vh[B_*H_*S_*DK_];
__device__ float g_ctx[BS_*D_];        // concat [B,S,D]
__device__ float g_x[BS_*D_];          // pre-LN (full fp32)
__device__ int   g_mflag[B_*16*32];    // per (b, qtile128, ktile64): any mask zero?

// ---------------- helpers ----------------
// NOTE: tf32 mma reads top 19 bits of operands (implicit truncation); no
// explicit cvt needed. rel_err budget 1e-3 >> truncation error ~1e-5.
__device__ __forceinline__ void mma8(float& c0, float& c1, float& c2, float& c3,
                                     unsigned a0, unsigned a1, unsigned a2, unsigned a3,
                                     unsigned b0, unsigned b1) {
    asm volatile(
        "mma.sync.aligned.m16n8k8.row.col.f32.tf32.tf32.f32 "
        "{%0,%1,%2,%3},{%4,%5,%6,%7},{%8,%9},{%0,%1,%2,%3};"
        : "+f"(c0), "+f"(c1), "+f"(c2), "+f"(c3)
        : "r"(a0), "r"(a1), "r"(a2), "r"(a3), "r"(b0), "r"(b1));
}

__device__ __forceinline__ void cpasync16(unsigned dst, const void* src) {
    asm volatile("cp.async.cg.shared.global [%0], [%1], 16;" :: "r"(dst), "l"(src));
}
#define CP_COMMIT() asm volatile("cp.async.commit_group;")
#define CP_WAIT2()  asm volatile("cp.async.wait_group 2;")
#define CP_WAIT1()  asm volatile("cp.async.wait_group 1;")
#define CP_WAIT0()  asm volatile("cp.async.wait_group 0;")

// ===========================================================================
// Mask summary: flag per (b, qtile 128, ktile 64) whether any zero present
// ===========================================================================
__global__ void maskflag_kernel(const int* __restrict__ mask)
{
    const int kt = blockIdx.x, qt = blockIdx.y, b = blockIdx.z;
    const int* mb = mask + ((size_t)b * S_ + qt * 128) * S_ + kt * 64;
    const int t = threadIdx.x;
    int anyz = 0;
#pragma unroll
    for (int i = 0; i < 8; i++) {
        int lin = t + 256 * i;
        int row = lin >> 4;
        int c4  = (lin & 15) * 4;
        int4 v = *(const int4*)(mb + (size_t)row * S_ + c4);
        anyz |= (v.x == 0) | (v.y == 0) | (v.z == 0) | (v.w == 0);
    }
    anyz = __syncthreads_or(anyz);
    if (t == 0) g_mflag[(b * 16 + qt) * 32 + kt] = anyz;
}

// ===========================================================================
// tf32 GEMM (raw fp32 operands; HW truncates), cp.async 2-stage,
// BM=BN=128, BK=32, 8 warps (64x32 each).
// mode 0: grid.z selects q/k/v; scatter C+bias to head layout
// mode 1: g_x = (g_ctx @ Wo^T) + bias + res (fp32)
// ===========================================================================
#define GAST 36
#define GEMM_STAGE_FLOATS (128*GAST*2)     // 9216
#define GEMM_SMEM (2*GEMM_STAGE_FLOATS*4)  // 73728 bytes

__global__ __launch_bounds__(256) void gemm_tc(const float* __restrict__ x0,
                                               const float* __restrict__ x1,
                                               const float* __restrict__ x2,
                                               const float* __restrict__ w0,
                                               const float* __restrict__ w1,
                                               const float* __restrict__ w2,
                                               const float* __restrict__ bias0,
                                               const float* __restrict__ bias1,
                                               const float* __restrict__ bias2,
                                               const float* __restrict__ res,
                                               int mode)
{
    extern __shared__ float gsm[];

    const int which = (mode == 1) ? 0 : blockIdx.z;
    const float* bias = (which == 0) ? bias0 : (which == 1) ? bias1 : bias2;
    const float* X = (mode == 1) ? (const float*)g_ctx
                                 : (which == 0) ? x0 : (which == 1) ? x1 : x2;
    const float* W = (which == 0) ? w0 : (which == 1) ? w1 : w2;
    float* outp = (which == 0) ? g_Qh : (which == 1) ? g_Kh : g_Vh;

    const int bm = blockIdx.y * 128;
    const int bn = blockIdx.x * 128;
    const int t    = threadIdx.x;
    const int w    = t >> 5;
    const int lane = t & 31;
    const int gid  = lane >> 2;
    const int tid  = lane & 3;
    const int wm   = (w & 1) * 64;
    const int wn   = (w >> 1) * 32;

    const unsigned smaddr = (unsigned)__cvta_generic_to_shared(gsm);

    float c[4][4][4];
#pragma unroll
    for (int i = 0; i < 4; i++)
#pragma unroll
        for (int j = 0; j < 4; j++)
#pragma unroll
            for (int r = 0; r < 4; r++) c[i][j][r] = 0.f;

    {
        unsigned ab = smaddr;
        unsigned bb = ab + 128 * GAST * 4;
#pragma unroll
        for (int i = 0; i < 4; i++) {
            int idx = t + 256 * i;
            int row = idx >> 3;
            int c4  = (idx & 7) << 2;
            cpasync16(ab + (row * GAST + c4) * 4, X + (size_t)(bm + row) * D_ + c4);
            cpasync16(bb + (row * GAST + c4) * 4, W + (size_t)(bn + row) * D_ + c4);
        }
        CP_COMMIT();
    }

    for (int it = 0; it < D_ / 32; it++) {
        const int cur = it & 1;
        if (it + 1 < D_ / 32) {
            const int k0 = (it + 1) * 32;
            unsigned ab = smaddr + (cur ^ 1) * GEMM_STAGE_FLOATS * 4;
            unsigned bb = ab + 128 * GAST * 4;
#pragma unroll
            for (int i = 0; i < 4; i++) {
                int idx = t + 256 * i;
                int row = idx >> 3;
                int c4  = (idx & 7) << 2;
                cpasync16(ab + (row * GAST + c4) * 4, X + (size_t)(bm + row) * D_ + k0 + c4);
                cpasync16(bb + (row * GAST + c4) * 4, W + (size_t)(bn + row) * D_ + k0 + c4);
            }
            CP_COMMIT();
            CP_WAIT1();
        } else {
            CP_WAIT0();
        }
        __syncthreads();

        const float* Ab = gsm + cur * GEMM_STAGE_FLOATS;
        const float* Bb = Ab + 128 * GAST;

#pragma unroll
        for (int ks = 0; ks < 4; ks++) {
            const int k = ks * 8;
            unsigned a0[4], a1[4], a2[4], a3[4], bf0[4], bf1[4];
#pragma unroll
            for (int i = 0; i < 4; i++) {
                int r0 = wm + i * 16 + gid;
                a0[i] = __float_as_uint(Ab[(r0    ) * GAST + k + tid]);
                a1[i] = __float_as_uint(Ab[(r0 + 8) * GAST + k + tid]);
                a2[i] = __float_as_uint(Ab[(r0    ) * GAST + k + tid + 4]);
                a3[i] = __float_as_uint(Ab[(r0 + 8) * GAST + k + tid + 4]);
            }
#pragma unroll
            for (int j = 0; j < 4; j++) {
                int n0 = wn + j * 8 + gid;
                bf0[j] = __float_as_uint(Bb[n0 * GAST + k + tid]);
                bf1[j] = __float_as_uint(Bb[n0 * GAST + k + tid + 4]);
            }
#pragma unroll
            for (int i = 0; i < 4; i++)
#pragma unroll
                for (int j = 0; j < 4; j++)
                    mma8(c[i][j][0], c[i][j][1], c[i][j][2], c[i][j][3],
                         a0[i], a1[i], a2[i], a3[i], bf0[j], bf1[j]);
        }
        __syncthreads();
    }

#pragma unroll
    for (int i = 0; i < 4; i++) {
        int r0 = bm + wm + i * 16 + gid;
        int r1 = r0 + 8;
#pragma unroll
        for (int j = 0; j < 4; j++) {
            int n0 = bn + wn + j * 8 + tid * 2;
            int n1 = n0 + 1;
            if (mode == 0) {
                int b0i = r0 >> 11, s0 = r0 & (S_ - 1);
                int b1i = r1 >> 11, s1 = r1 & (S_ - 1);
                int h0 = n0 >> 6, d0 = n0 & 63;
                int h1 = n1 >> 6, d1 = n1 & 63;
                outp[(((size_t)(b0i * H_ + h0)) * S_ + s0) * DK_ + d0] = c[i][j][0] + bias[n0];
                outp[(((size_t)(b0i * H_ + h1)) * S_ + s0) * DK_ + d1] = c[i][j][1] + bias[n1];
                outp[(((size_t)(b1i * H_ + h0)) * S_ + s1) * DK_ + d0] = c[i][j][2] + bias[n0];
                outp[(((size_t)(b1i * H_ + h1)) * S_ + s1) * DK_ + d1] = c[i][j][3] + bias[n1];
            } else {
                g_x[(size_t)r0 * D_ + n0] = c[i][j][0] + bias[n0] + res[(size_t)r0 * D_ + n0];
                g_x[(size_t)r0 * D_ + n1] = c[i][j][1] + bias[n1] + res[(size_t)r0 * D_ + n1];
                g_x[(size_t)r1 * D_ + n0] = c[i][j][2] + bias[n0] + res[(size_t)r1 * D_ + n0];
                g_x[(size_t)r1 * D_ + n1] = c[i][j][3] + bias[n1] + res[(size_t)r1 * D_ + n1];
            }
        }
    }
}

// ===========================================================================
// Flash attention, tf32 mma. Q frags in registers, P kept in registers via
// quad shuffles (no Ps smem), 3-stage cp.async K/V pipeline.
// Bq=128 (8 warps x 16 rows), Bk=64.
// smem: Ks[3][64][68] + Vs[3][64][72] = 26880 floats = 105 KB -> 2 blocks/SM
// (Q staged through Ks[0..1] before prefetch: 2*64*68 == 128*68 exactly)
// ===========================================================================
#define QST 68
#define VST 72
#define F_KS   0
#define F_VS   (3*64*QST)
#define FLASH_FLOATS (F_VS + 3*64*VST)   // 26880
#define FLASH_SMEM   (FLASH_FLOATS*4)    // 107520 B

__global__ __launch_bounds__(256, 2) void flash_tc(const int* __restrict__ mask)
{
    extern __shared__ float sm[];

    const int b  = blockIdx.z;
    const int h  = blockIdx.y;
    const int q0 = blockIdx.x * 128;
    const int t    = threadIdx.x;
    const int w    = t >> 5;
    const int lane = t & 31;
    const int gid  = lane >> 2;
    const int tid  = lane & 3;

    const float* Qg = g_Qh + ((size_t)(b * H_ + h)) * S_ * DK_;
    const float* Kg = g_Kh + ((size_t)(b * H_ + h)) * S_ * DK_;
    const float* Vg = g_Vh + ((size_t)(b * H_ + h)) * S_ * DK_;
    const int* mbase = mask + (size_t)b * S_ * S_;
    const int* mflag = g_mflag + (b * 16 + blockIdx.x) * 32;

    const unsigned smaddr = (unsigned)__cvta_generic_to_shared(sm);
    const int rloc0 = w * 16 + gid;
    const int rloc1 = rloc0 + 8;

    // ---- stage Q through Ks[0..1] region, pull frags to registers ----
    {
        float* Qs = sm + F_KS;   // 128 x QST fits in 2 K stages
#pragma unroll
        for (int i = 0; i < 8; i++) {
            int l4  = t + 256 * i;
            int row = l4 >> 4;
            int dg  = (l4 & 15) << 2;
            *(float4*)(Qs + row * QST + dg) =
                *(const float4*)(Qg + (size_t)(q0 + row) * DK_ + dg);
        }
        __syncthreads();
        // fall through; qr loads below
    }
    unsigned qr[32];
    {
        const float* Qs = sm + F_KS;
#pragma unroll
        for (int kk = 0; kk < 8; kk++) {
            const int k = kk * 8;
            qr[kk * 4 + 0] = __float_as_uint(Qs[rloc0 * QST + k + tid]);
            qr[kk * 4 + 1] = __float_as_uint(Qs[rloc1 * QST + k + tid]);
            qr[kk * 4 + 2] = __float_as_uint(Qs[rloc0 * QST + k + tid + 4]);
            qr[kk * 4 + 3] = __float_as_uint(Qs[rloc1 * QST + k + tid + 4]);
        }
    }
    __syncthreads();   // everyone read Q; safe to overwrite with K prefetch

    // ---- prefetch K/V tiles 0 and 1 ----
#pragma unroll
    for (int pt = 0; pt < 2; pt++) {
        unsigned ka = smaddr + (F_KS + pt * 64 * QST) * 4;
        unsigned va = smaddr + (F_VS + pt * 64 * VST) * 4;
        const int k0p = pt * 64;
#pragma unroll
        for (int i = 0; i < 4; i++) {
            int l4  = t + 256 * i;
            int row = l4 >> 4;
            int dg  = (l4 & 15) << 2;
            cpasync16(ka + (row * QST + dg) * 4, Kg + (size_t)(k0p + row) * DK_ + dg);
            cpasync16(va + (row * VST + dg) * 4, Vg + (size_t)(k0p + row) * DK_ + dg);
        }
        CP_COMMIT();
    }

    float o[8][4];
#pragma unroll
    for (int j = 0; j < 8; j++)
#pragma unroll
        for (int r = 0; r < 4; r++) o[j][r] = 0.f;
    float mprev0 = -1e30f, mprev1 = -1e30f, lsum0 = 0.f, lsum1 = 0.f;

    const int NT = S_ / 64;
    for (int kt = 0; kt < NT; kt++) {
        const int cur = kt % 3;
        __syncthreads();   // all warps done with tile kt-1 (stage (kt+2)%3)

        if (kt + 2 < NT) {
            const int nstage = (kt + 2) % 3;
            const int k0n = (kt + 2) * 64;
            unsigned ka = smaddr + (F_KS + nstage * 64 * QST) * 4;
            unsigned va = smaddr + (F_VS + nstage * 64 * VST) * 4;
#pragma unroll
            for (int i = 0; i < 4; i++) {
                int l4  = t + 256 * i;
                int row = l4 >> 4;
                int dg  = (l4 & 15) << 2;
                cpasync16(ka + (row * QST + dg) * 4, Kg + (size_t)(k0n + row) * DK_ + dg);
                cpasync16(va + (row * VST + dg) * 4, Vg + (size_t)(k0n + row) * DK_ + dg);
            }
            CP_COMMIT();
            CP_WAIT2();
        } else if (kt + 1 < NT) {
            CP_WAIT1();
        } else {
            CP_WAIT0();
        }
        __syncthreads();   // stage cur visible

        const float* Ks = sm + F_KS + cur * 64 * QST;
        const float* Vs = sm + F_VS + cur * 64 * VST;
        const int k0 = kt * 64;

        // ---- S = Q @ K^T (Q from registers) ----
        float s[8][4];
#pragma unroll
        for (int j = 0; j < 8; j++)
#pragma unroll
            for (int r = 0; r < 4; r++) s[j][r] = 0.f;

#pragma unroll
        for (int kk = 0; kk < 8; kk++) {
            const int k = kk * 8;
            const unsigned qa0 = qr[kk * 4 + 0];
            const unsigned qa1 = qr[kk * 4 + 1];
            const unsigned qa2 = qr[kk * 4 + 2];
            const unsigned qa3 = qr[kk * 4 + 3];
#pragma unroll
            for (int j = 0; j < 8; j++) {
                unsigned b0 = __float_as_uint(Ks[(j * 8 + gid) * QST + k + tid]);
                unsigned b1 = __float_as_uint(Ks[(j * 8 + gid) * QST + k + tid + 4]);
                mma8(s[j][0], s[j][1], s[j][2], s[j][3], qa0, qa1, qa2, qa3, b0, b1);
            }
        }

        // ---- scale (+mask only if tile has zeros) ----
        const float scale = 0.125f;
#pragma unroll
        for (int j = 0; j < 8; j++) {
            s[j][0] *= scale; s[j][1] *= scale;
            s[j][2] *= scale; s[j][3] *= scale;
        }
        if (mflag[kt]) {
            const int gr0 = q0 + rloc0;
            const int gr1 = q0 + rloc1;
#pragma unroll
            for (int j = 0; j < 8; j++) {
                int col = k0 + j * 8 + tid * 2;
                const int* m0p = mbase + (size_t)gr0 * S_ + col;
                const int* m1p = mbase + (size_t)gr1 * S_ + col;
                if (m0p[0] == 0) s[j][0] = -1e9f;
                if (m0p[1] == 0) s[j][1] = -1e9f;
                if (m1p[0] == 0) s[j][2] = -1e9f;
                if (m1p[1] == 0) s[j][3] = -1e9f;
            }
        }

        // ---- online softmax (P stays in s[] registers) ----
        float mx0 = -1e30f, mx1 = -1e30f;
#pragma unroll
        for (int j = 0; j < 8; j++) {
            mx0 = fmaxf(mx0, fmaxf(s[j][0], s[j][1]));
            mx1 = fmaxf(mx1, fmaxf(s[j][2], s[j][3]));
        }
#pragma unroll
        for (int off = 1; off <= 2; off <<= 1) {
            mx0 = fmaxf(mx0, __shfl_xor_sync(0xffffffffu, mx0, off));
            mx1 = fmaxf(mx1, __shfl_xor_sync(0xffffffffu, mx1, off));
        }
        float mn0 = fmaxf(mprev0, mx0);
        float mn1 = fmaxf(mprev1, mx1);
        float f0 = __expf(mprev0 - mn0);
        float f1 = __expf(mprev1 - mn1);
        float rs0 = 0.f, rs1 = 0.f;
#pragma unroll
        for (int j = 0; j < 8; j++) {
            s[j][0] = __expf(s[j][0] - mn0);
            s[j][1] = __expf(s[j][1] - mn0);
            s[j][2] = __expf(s[j][2] - mn1);
            s[j][3] = __expf(s[j][3] - mn1);
            rs0 += s[j][0] + s[j][1];
            rs1 += s[j][2] + s[j][3];
        }
#pragma unroll
        for (int off = 1; off <= 2; off <<= 1) {
            rs0 += __shfl_xor_sync(0xffffffffu, rs0, off);
            rs1 += __shfl_xor_sync(0xffffffffu, rs1, off);
        }
        lsum0 = lsum0 * f0 + rs0;
        lsum1 = lsum1 * f1 + rs1;
        mprev0 = mn0;
        mprev1 = mn1;
#pragma unroll
        for (int j = 0; j < 8; j++) {
            o[j][0] *= f0; o[j][1] *= f0;
            o[j][2] *= f1; o[j][3] *= f1;
        }

        // ---- O += P @ V : P A-frags built from s[] via quad shuffles ----
        // Acc layout: s[kk][e] = P(gid + 8*(e>=2), kk*8 + 2*tid + (e&1)).
        // A-frag needs P(gid, kk*8+tid) etc. -> src lane (tid>>1) / (tid>>1)+2
        // within the 4-lane quad, element selected by tid&1.
        {
            const int e   = tid & 1;
            const int so  = tid >> 1;
            const int so2 = so + 2;
#pragma unroll
            for (int kk = 0; kk < 8; kk++) {
                const int k = kk * 8;
                float x0 = __shfl_sync(0xffffffffu, s[kk][0], so,  4);
                float x1 = __shfl_sync(0xffffffffu, s[kk][1], so,  4);
                float x2 = __shfl_sync(0xffffffffu, s[kk][2], so,  4);
                float x3 = __shfl_sync(0xffffffffu, s[kk][3], so,  4);
                float y0 = __shfl_sync(0xffffffffu, s[kk][0], so2, 4);
                float y1 = __shfl_sync(0xffffffffu, s[kk][1], so2, 4);
                float y2 = __shfl_sync(0xffffffffu, s[kk][2], so2, 4);
                float y3 = __shfl_sync(0xffffffffu, s[kk][3], so2, 4);
                unsigned pa0 = __float_as_uint(e ? x1 : x0);
                unsigned pa1 = __float_as_uint(e ? x3 : x2);
                unsigned pa2 = __float_as_uint(e ? y1 : y0);
                unsigned pa3 = __float_as_uint(e ? y3 : y2);
#pragma unroll
                for (int j = 0; j < 8; j++) {
                    unsigned b0 = __float_as_uint(Vs[(k + tid)     * VST + j * 8 + gid]);
                    unsigned b1 = __float_as_uint(Vs[(k + tid + 4) * VST + j * 8 + gid]);
                    mma8(o[j][0], o[j][1], o[j][2], o[j][3], pa0, pa1, pa2, pa3, b0, b1);
                }
            }
        }
    }

    // epilogue -> g_ctx (raw fp32; out-proj mma truncates)
    float inv0 = 1.0f / lsum0;
    float inv1 = 1.0f / lsum1;
    float* out0 = g_ctx + ((size_t)b * S_ + (q0 + rloc0)) * D_ + h * DK_;
    float* out1 = g_ctx + ((size_t)b * S_ + (q0 + rloc1)) * D_ + h * DK_;
#pragma unroll
    for (int j = 0; j < 8; j++) {
        int col = j * 8 + tid * 2;
        out0[col + 0] = o[j][0] * inv0;
        out0[col + 1] = o[j][1] * inv0;
        out1[col + 0] = o[j][2] * inv1;
        out1[col + 1] = o[j][3] * inv1;
    }
}

// ===========================================================================
// LayerNorm over D=1024 per row
// ===========================================================================
__global__ __launch_bounds__(256) void ln_kernel(const float* __restrict__ gamma,
                                                 const float* __restrict__ beta,
                                                 float* __restrict__ out)
{
    const int row = blockIdx.x;
    const int t   = threadIdx.x;
    const float* x = g_x + (size_t)row * D_;

    float4 v = *(const float4*)(x + t * 4);
    float s  = v.x + v.y + v.z + v.w;
    float ss = v.x * v.x + v.y * v.y + v.z * v.z + v.w * v.w;
#pragma unroll
    for (int off = 16; off >= 1; off >>= 1) {
        s  += __shfl_xor_sync(0xffffffffu, s,  off);
        ss += __shfl_xor_sync(0xffffffffu, ss, off);
    }
    __shared__ float red[8][2];
    int w = t >> 5, ln = t & 31;
    if (ln == 0) { red[w][0] = s; red[w][1] = ss; }
    __syncthreads();
    s = 0.f; ss = 0.f;
#pragma unroll
    for (int i = 0; i < 8; i++) { s += red[i][0]; ss += red[i][1]; }

    float mean = s * (1.0f / D_);
    float var  = ss * (1.0f / D_) - mean * mean;
    float rstd = rsqrtf(var + 1e-5f);

    float4 g  = *(const float4*)(gamma + t * 4);
    float4 be = *(const float4*)(beta + t * 4);
    float4 ov;
    ov.x = (v.x - mean) * rstd * g.x + be.x;
    ov.y = (v.y - mean) * rstd * g.y + be.y;
    ov.z = (v.z - mean) * rstd * g.z + be.z;
    ov.w = (v.w - mean) * rstd * g.w + be.w;
    *(float4*)(out + (size_t)row * D_ + t * 4) = ov;
}

// ===========================================================================
extern "C" void kernel_launch(void* const* d_in, const int* in_sizes, int n_in,
                              void* d_out, int out_size)
{
    const float* q     = (const float*)d_in[0];
    const float* k     = (const float*)d_in[1];
    const float* v     = (const float*)d_in[2];
    const int*   mask  = (const int*)  d_in[3];
    const float* Wq    = (const float*)d_in[4];
    const float* bq    = (const float*)d_in[5];
    const float* Wk    = (const float*)d_in[6];
    const float* bk    = (const float*)d_in[7];
    const float* Wv    = (const float*)d_in[8];
    const float* bv    = (const float*)d_in[9];
    const float* Wo    = (const float*)d_in[10];
    const float* bo    = (const float*)d_in[11];
    const float* gamma = (const float*)d_in[12];
    const float* beta  = (const float*)d_in[13];
    float* out = (float*)d_out;

    maskflag_kernel<<<dim3(32, 16, B_), 256>>>(mask);

    cudaFuncSetAttribute(gemm_tc, cudaFuncAttributeMaxDynamicSharedMemorySize, GEMM_SMEM);
    // QKV projections in ONE launch (grid.z = 3); raw operands, HW truncates
    gemm_tc<<<dim3(D_ / 128, BS_ / 128, 3), 256, GEMM_SMEM>>>(
        q, k, v, Wq, Wk, Wv, bq, bk, bv, nullptr, 0);

    cudaFuncSetAttribute(flash_tc, cudaFuncAttributeMaxDynamicSharedMemorySize, FLASH_SMEM);
    flash_tc<<<dim3(S_ / 128, H_, B_), 256, FLASH_SMEM>>>(mask);

    // out-proj: X = g_ctx (device-side), W = Wo
    gemm_tc<<<dim3(D_ / 128, BS_ / 128, 1), 256, GEMM_SMEM>>>(
        nullptr, nullptr, nullptr, Wo, nullptr, nullptr, bo, nullptr, nullptr, q, 1);

    ln_kernel<<<BS_, 256>>>(gamma, beta, out);
}